// round 5
// baseline (speedup 1.0000x reference)
#include <cuda_runtime.h>
#include <cuda_bf16.h>
#include <stdint.h>

typedef unsigned long long ull;

// Problem dims
#define BDIM 32
#define TDIM 512
#define IDIM 512
#define HDIM 1024
#define MDIM (TDIM * BDIM)   // 16384 rows (m = t*B + b)

// ---------------- scratch (static device globals; no allocation) ----------------
__device__ float g_xT[(size_t)MDIM * IDIM];   // x transposed to [t,b,i] rows
__device__ float g_xw[(size_t)MDIM * HDIM];   // xw0, later reused as xw1
__device__ float g_h1[(size_t)MDIM * HDIM];   // layer-0 hidden states [t,b,h]
__device__ float g_hT4[4][2][HDIM * 8];       // per-group ping-pong h^T: [k][8 local b]

__device__ unsigned g_flags0[128];
__device__ unsigned g_flags1[128];

// ---------------- f32x2 helpers ----------------
__device__ __forceinline__ void ffma2(ull& d, ull a, ull b) {
    asm("fma.rn.f32x2 %0, %1, %2, %0;" : "+l"(d) : "l"(a), "l"(b));
}
__device__ __forceinline__ void add2(ull& d, ull a) {
    asm("add.rn.f32x2 %0, %0, %1;" : "+l"(d) : "l"(a));
}
__device__ __forceinline__ ull splat2(float x) {
    ull r;
    asm("mov.b64 %0, {%1, %1};" : "=l"(r) : "f"(x));
    return r;
}
__device__ __forceinline__ float2 unpack2(ull v) {
    float lo, hi;
    asm("mov.b64 {%0, %1}, %2;" : "=f"(lo), "=f"(hi) : "l"(v));
    return make_float2(lo, hi);
}
__device__ __forceinline__ ull pack2(float lo, float hi) {
    ull r;
    asm("mov.b64 %0, {%1, %2};" : "=l"(r) : "f"(lo), "f"(hi));
    return r;
}
__device__ __forceinline__ ulonglong2 ldcg16(const void* p) {
    ulonglong2 v;
    asm volatile("ld.global.cg.v2.u64 {%0,%1}, [%2];"
                 : "=l"(v.x), "=l"(v.y) : "l"(p));
    return v;
}

// ---------------- init flags (inside graph; replayed every run) ----------------
__global__ void init_flags() {
    if (threadIdx.x < 128) {
        g_flags0[threadIdx.x] = 0;
        g_flags1[threadIdx.x] = 0;
    }
}

// ---------------- transpose x[B,T,I] -> xT[(t*B+b), I] ----------------
__global__ __launch_bounds__(128) void transpose_x(const float* __restrict__ x) {
    int m = blockIdx.x;
    int t = m >> 5;
    int b = m & 31;
    const float4* src = (const float4*)(x + ((size_t)b * TDIM + t) * IDIM);
    float4* dst = (float4*)(g_xT + (size_t)m * IDIM);
    dst[threadIdx.x] = src[threadIdx.x];
}

// ---------------- SGEMM: C[M,1024] = A[M,K] @ W[1024,K]^T + (b1+b2) ----------------
#define GBK 8
#define SAP 132

__global__ __launch_bounds__(256) void gemm_bias(
    const float* __restrict__ A, const float* __restrict__ W,
    const float* __restrict__ b1, const float* __restrict__ b2,
    float* __restrict__ C, int K)
{
    __shared__ __align__(16) float As[GBK * SAP];
    __shared__ __align__(16) float Bs[GBK * SAP];

    int tid  = threadIdx.x;
    int tx   = tid & 15;
    int ty   = tid >> 4;
    int brow = blockIdx.y * 128;
    int bcol = blockIdx.x * 128;

    int lr = tid >> 1;
    int lk = (tid & 1) * 4;

    const float* Aptr = A + (size_t)(brow + lr) * K + lk;
    const float* Wptr = W + (size_t)(bcol + lr) * K + lk;

    ull accp[4][8];
    #pragma unroll
    for (int p = 0; p < 4; p++)
        #pragma unroll
        for (int j = 0; j < 8; j++) accp[p][j] = 0ull;

    for (int k0 = 0; k0 < K; k0 += GBK) {
        float4 av = *(const float4*)(Aptr + k0);
        float4 wv = *(const float4*)(Wptr + k0);
        As[(lk + 0) * SAP + lr] = av.x;
        As[(lk + 1) * SAP + lr] = av.y;
        As[(lk + 2) * SAP + lr] = av.z;
        As[(lk + 3) * SAP + lr] = av.w;
        Bs[(lk + 0) * SAP + lr] = wv.x;
        Bs[(lk + 1) * SAP + lr] = wv.y;
        Bs[(lk + 2) * SAP + lr] = wv.z;
        Bs[(lk + 3) * SAP + lr] = wv.w;
        __syncthreads();

        #pragma unroll
        for (int kk = 0; kk < GBK; kk++) {
            const float* abase = &As[kk * SAP + ty * 8];
            ulonglong2 a01 = *(const ulonglong2*)abase;
            ulonglong2 a23 = *(const ulonglong2*)(abase + 4);
            ull ap[4] = {a01.x, a01.y, a23.x, a23.y};

            const float* bbase = &Bs[kk * SAP + tx * 8];
            float4 bv0 = *(const float4*)bbase;
            float4 bv1 = *(const float4*)(bbase + 4);
            ull bsp[8] = {
                splat2(bv0.x), splat2(bv0.y), splat2(bv0.z), splat2(bv0.w),
                splat2(bv1.x), splat2(bv1.y), splat2(bv1.z), splat2(bv1.w)};

            #pragma unroll
            for (int p = 0; p < 4; p++)
                #pragma unroll
                for (int j = 0; j < 8; j++)
                    ffma2(accp[p][j], ap[p], bsp[j]);
        }
        __syncthreads();
    }

    float bs[8];
    #pragma unroll
    for (int j = 0; j < 8; j++) {
        int c = bcol + tx * 8 + j;
        bs[j] = __ldg(b1 + c) + __ldg(b2 + c);
    }

    #pragma unroll
    for (int p = 0; p < 4; p++) {
        float2 u[8];
        #pragma unroll
        for (int j = 0; j < 8; j++) u[j] = unpack2(accp[p][j]);

        int row0 = brow + ty * 8 + 2 * p;
        float* cp0 = C + (size_t)row0 * HDIM + bcol + tx * 8;
        float* cp1 = cp0 + HDIM;
        float4 o;
        o.x = u[0].x + bs[0]; o.y = u[1].x + bs[1];
        o.z = u[2].x + bs[2]; o.w = u[3].x + bs[3];
        *(float4*)(cp0) = o;
        o.x = u[4].x + bs[4]; o.y = u[5].x + bs[5];
        o.z = u[6].x + bs[6]; o.w = u[7].x + bs[7];
        *(float4*)(cp0 + 4) = o;
        o.x = u[0].y + bs[0]; o.y = u[1].y + bs[1];
        o.z = u[2].y + bs[2]; o.w = u[3].y + bs[3];
        *(float4*)(cp1) = o;
        o.x = u[4].y + bs[4]; o.y = u[5].y + bs[5];
        o.z = u[6].y + bs[6]; o.w = u[7].y + bs[7];
        *(float4*)(cp1 + 4) = o;
    }
}

// ---------------- grouped recurrence ----------------
// 4 independent groups of 32 CTAs. Group g owns batches [8g, 8g+8).
// CTA cg (0..31) in a group owns columns [32cg, 32cg+32) with its full-height
// Whh slice (1024 x 32 = 128KB) resident in smem (k-major: Wsm[k*32 + j]).
// Compute thread (cq=tid&3, bq=(tid>>2)&1, ks=tid>>3): 8 cols x 4 batches x
// 32 k. h comes from the group's 32KB ping-pong hT buffer [k][8 local b] via
// one LDG.128 per k (L2-hot). 32-way k-split partials reduced via XOR-swizzled
// smem by threads 0..127 (2 outputs each). Sync: 32 per-group flags.
#define RC4_WS_BYTES  (HDIM * 32 * 4)          // 131072
#define RC4_PS_BYTES  (256 * 8 * 16)           // 32768
#define RC4_SMEM_BYTES (RC4_WS_BYTES + RC4_PS_BYTES)

__global__ __launch_bounds__(256) void recur4(
    const float* __restrict__ xw,   // [t*B+b, H] input projection (+biases)
    const float* __restrict__ Whh,  // [H, H]
    float* __restrict__ hio,        // layer0: g_h1 [t,b,h] ; layer1: d_out [b,t,h]
    unsigned* __restrict__ flags,   // 128 flags (32 per group)
    int bth)
{
    extern __shared__ __align__(16) float sm[];
    float* Wsm = sm;                        // [1024][32] floats
    char*  Psm = (char*)(sm + HDIM * 32);   // 32KB partials

    int tid = threadIdx.x;
    int g   = blockIdx.x >> 5;      // group 0..3
    int cg  = blockIdx.x & 31;      // CTA within group

    // compute-thread coords
    int cq = tid & 3;               // col quad (8 cols each)
    int bq = (tid >> 2) & 1;        // batch half (4 batches each)
    int ks = tid >> 3;              // k-slice 0..31 (32 k each)

    // reduction-thread coords (tid < 128)
    int col_l = tid >> 2;           // 0..31
    int bp    = tid & 3;            // (bq_r, p_r)
    int bq_r  = bp >> 1;
    int p_r   = bp & 1;
    int cq_r  = col_l >> 3;
    int c_r   = col_l & 7;
    int colg  = cg * 32 + col_l;    // global column
    int bl0   = 4 * bq_r + 2 * p_r; // local batch pair (bl0, bl0+1)
    int b0    = g * 8 + bl0;        // global batch

    // load Whh slice, k-major: Wsm[k*32 + j] = Whh[32cg + j][k]
    for (int idx = tid; idx < HDIM * 32; idx += 256) {
        int j = idx & 31;
        int k = idx >> 5;
        Wsm[k * 32 + j] = __ldg(Whh + (size_t)(cg * 32 + j) * HDIM + k);
    }
    __syncthreads();

    unsigned* myflag = flags + g * 32 + (tid & 31);
    float* hT0 = &g_hT4[g][0][0];
    float* hT1 = &g_hT4[g][1][0];

    // per-thread bases
    const float4* wls = (const float4*)Wsm + 256 * ks + 2 * cq;  // +8 per k
    const size_t  hoff = (size_t)ks * 1024 + (size_t)bq * 16;    // bytes into hT

    for (int t = 0; t < TDIM; t++) {
        // xw prefetch (independent of h)
        float xv0 = 0.f, xv1 = 0.f;
        if (tid < 128) {
            xv0 = __ldg(xw + ((size_t)t * BDIM + b0) * HDIM + colg);
            xv1 = __ldg(xw + ((size_t)t * BDIM + b0 + 1) * HDIM + colg);
        }

        if (t > 0) {
            // wait for all 32 producers of this group to publish step t-1
            unsigned f;
            do {
                asm volatile("ld.acquire.gpu.u32 %0, [%1];"
                             : "=r"(f) : "l"(myflag));
            } while (f < (unsigned)t);
            __syncthreads();

            const char* hp = (const char*)(((t - 1) & 1) ? hT1 : hT0) + hoff;

            ull acc[8][2];
            #pragma unroll
            for (int c = 0; c < 8; c++) { acc[c][0] = 0ull; acc[c][1] = 0ull; }

            #pragma unroll 8
            for (int i = 0; i < 32; i++) {
                ulonglong2 h2 = ldcg16(hp + i * 32);   // 4 local batches
                float4 w0 = wls[i * 8];
                float4 w1 = wls[i * 8 + 1];
                ull s;
                s = splat2(w0.x); ffma2(acc[0][0], h2.x, s); ffma2(acc[0][1], h2.y, s);
                s = splat2(w0.y); ffma2(acc[1][0], h2.x, s); ffma2(acc[1][1], h2.y, s);
                s = splat2(w0.z); ffma2(acc[2][0], h2.x, s); ffma2(acc[2][1], h2.y, s);
                s = splat2(w0.w); ffma2(acc[3][0], h2.x, s); ffma2(acc[3][1], h2.y, s);
                s = splat2(w1.x); ffma2(acc[4][0], h2.x, s); ffma2(acc[4][1], h2.y, s);
                s = splat2(w1.y); ffma2(acc[5][0], h2.x, s); ffma2(acc[5][1], h2.y, s);
                s = splat2(w1.z); ffma2(acc[6][0], h2.x, s); ffma2(acc[6][1], h2.y, s);
                s = splat2(w1.w); ffma2(acc[7][0], h2.x, s); ffma2(acc[7][1], h2.y, s);
            }

            // store partials: chunk m of thread tid at 16B slot tid*8 + (m^(tid&7))
            #pragma unroll
            for (int m = 0; m < 8; m++) {
                int a16 = (tid << 3) + (m ^ (tid & 7));
                ulonglong2 v;
                v.x = acc[m][0];
                v.y = acc[m][1];
                *(ulonglong2*)(Psm + ((size_t)a16 << 4)) = v;
            }
        }
        __syncthreads();

        if (tid < 128) {
            float o0, o1;
            if (t > 0) {
                ull s0 = 0ull, s1 = 0ull;
                #pragma unroll 8
                for (int k2 = 0; k2 < 32; k2 += 2) {
                    int sA = cq_r + 4 * bq_r + 8 * k2;
                    int sB = sA + 8;
                    int aA = (sA << 3) + (c_r ^ (sA & 7));
                    int aB = (sB << 3) + (c_r ^ (sB & 7));
                    ull vA = *(const ull*)(Psm + ((size_t)aA << 4) + (p_r << 3));
                    ull vB = *(const ull*)(Psm + ((size_t)aB << 4) + (p_r << 3));
                    add2(s0, vA);
                    add2(s1, vB);
                }
                add2(s0, s1);
                float2 u = unpack2(s0);
                o0 = xv0 + u.x;
                o1 = xv1 + u.y;
            } else {
                o0 = xv0;
                o1 = xv1;
            }
            float h0 = tanhf(o0);
            float h1 = tanhf(o1);

            size_t d0;
            if (bth) d0 = ((size_t)b0 * TDIM + t) * HDIM + colg;
            else     d0 = ((size_t)t * BDIM + b0) * HDIM + colg;
            size_t d1 = d0 + (bth ? (size_t)TDIM * HDIM : (size_t)HDIM);
            hio[d0] = h0;
            hio[d1] = h1;

            // publish transposed pair for next step
            *(ull*)((char*)((t & 1) ? hT1 : hT0) + (size_t)colg * 32 + (bl0 << 2))
                = pack2(h0, h1);
        }

        __syncthreads();
        if (tid == 0) {
            asm volatile("st.release.gpu.u32 [%0], %1;"
                         :: "l"(flags + g * 32 + cg), "r"((unsigned)(t + 1)));
        }
    }
}

// ---------------- launch ----------------
extern "C" void kernel_launch(void* const* d_in, const int* in_sizes, int n_in,
                              void* d_out, int out_size)
{
    const float* x    = (const float*)d_in[0];
    const float* Wih0 = (const float*)d_in[1];
    const float* Whh0 = (const float*)d_in[2];
    const float* bih0 = (const float*)d_in[3];
    const float* bhh0 = (const float*)d_in[4];
    const float* Wih1 = (const float*)d_in[5];
    const float* Whh1 = (const float*)d_in[6];
    const float* bih1 = (const float*)d_in[7];
    const float* bhh1 = (const float*)d_in[8];
    float* out = (float*)d_out;

    float *xT, *xw, *h1;
    unsigned *f0, *f1;
    cudaGetSymbolAddress((void**)&xT, g_xT);
    cudaGetSymbolAddress((void**)&xw, g_xw);
    cudaGetSymbolAddress((void**)&h1, g_h1);
    cudaGetSymbolAddress((void**)&f0, g_flags0);
    cudaGetSymbolAddress((void**)&f1, g_flags1);

    cudaFuncSetAttribute(recur4, cudaFuncAttributeMaxDynamicSharedMemorySize,
                         RC4_SMEM_BYTES);

    init_flags<<<1, 128>>>();
    transpose_x<<<MDIM, 128>>>(x);
    gemm_bias<<<dim3(HDIM / 128, MDIM / 128), 256>>>(xT, Wih0, bih0, bhh0, xw, IDIM);
    recur4<<<128, 256, RC4_SMEM_BYTES>>>(xw, Whh0, h1, f0, 0);
    gemm_bias<<<dim3(HDIM / 128, MDIM / 128), 256>>>(h1, Wih1, bih1, bhh1, xw, HDIM);
    recur4<<<128, 256, RC4_SMEM_BYTES>>>(xw, Whh1, out, f1, 1);
}

// round 7
// speedup vs baseline: 1.2306x; 1.2306x over previous
#include <cuda_runtime.h>
#include <cuda_bf16.h>
#include <stdint.h>

typedef unsigned long long ull;

// Problem dims
#define BDIM 32
#define TDIM 512
#define IDIM 512
#define HDIM 1024
#define MDIM (TDIM * BDIM)   // 16384 rows (m = t*B + b)

// ---------------- scratch (static device globals; no allocation) ----------------
__device__ float g_xT[(size_t)MDIM * IDIM];   // x transposed to [t,b,i] rows
__device__ float g_xw[(size_t)MDIM * HDIM];   // xw0, later reused as xw1
__device__ float g_h1[(size_t)MDIM * HDIM];   // layer-0 hidden states [t,b,h]
__device__ float g_hp[4 * 2 * 8 * HDIM];      // h exchange: [bg][parity][b_local][col]

__device__ unsigned g_flags0[512];            // layer-0: [bg][cb] progress
__device__ unsigned g_flags1[512];            // layer-1

// ---------------- f32x2 helpers ----------------
__device__ __forceinline__ void ffma2(ull& d, ull a, ull b) {
    asm("fma.rn.f32x2 %0, %1, %2, %0;" : "+l"(d) : "l"(a), "l"(b));
}
__device__ __forceinline__ void add2(ull& d, ull a) {
    asm("add.rn.f32x2 %0, %0, %1;" : "+l"(d) : "l"(a));
}
__device__ __forceinline__ ull splat2(float x) {
    ull r;
    asm("mov.b64 %0, {%1, %1};" : "=l"(r) : "f"(x));
    return r;
}
__device__ __forceinline__ float2 unpack2(ull v) {
    float lo, hi;
    asm("mov.b64 {%0, %1}, %2;" : "=f"(lo), "=f"(hi) : "l"(v));
    return make_float2(lo, hi);
}
__device__ __forceinline__ ull pack2(float lo, float hi) {
    ull r;
    asm("mov.b64 %0, {%1, %2};" : "=l"(r) : "f"(lo), "f"(hi));
    return r;
}
__device__ __forceinline__ ulonglong2 ldcg16(const void* p) {
    ulonglong2 v;
    asm volatile("ld.global.cg.v2.u64 {%0,%1}, [%2];"
                 : "=l"(v.x), "=l"(v.y) : "l"(p));
    return v;
}

// ---------------- init flags (inside graph; replayed every run) ----------------
__global__ void init_flags() {
    int i = blockIdx.x * blockDim.x + threadIdx.x;
    if (i < 512) {
        g_flags0[i] = 0;
        g_flags1[i] = 0;
    }
}

// ---------------- transpose x[B,T,I] -> xT[(t*B+b), I] ----------------
__global__ __launch_bounds__(128) void transpose_x(const float* __restrict__ x) {
    int m = blockIdx.x;
    int t = m >> 5;
    int b = m & 31;
    const float4* src = (const float4*)(x + ((size_t)b * TDIM + t) * IDIM);
    float4* dst = (float4*)(g_xT + (size_t)m * IDIM);
    dst[threadIdx.x] = src[threadIdx.x];
}

// ---------------- SGEMM: C[M,1024] = A[M,K] @ W[1024,K]^T + (b1+b2) ----------------
#define GBK 8
#define SAP 132

__global__ __launch_bounds__(256) void gemm_bias(
    const float* __restrict__ A, const float* __restrict__ W,
    const float* __restrict__ b1, const float* __restrict__ b2,
    float* __restrict__ C, int K)
{
    __shared__ __align__(16) float As[GBK * SAP];
    __shared__ __align__(16) float Bs[GBK * SAP];

    int tid  = threadIdx.x;
    int tx   = tid & 15;
    int ty   = tid >> 4;
    int brow = blockIdx.y * 128;
    int bcol = blockIdx.x * 128;

    int lr = tid >> 1;
    int lk = (tid & 1) * 4;

    const float* Aptr = A + (size_t)(brow + lr) * K + lk;
    const float* Wptr = W + (size_t)(bcol + lr) * K + lk;

    ull accp[4][8];
    #pragma unroll
    for (int p = 0; p < 4; p++)
        #pragma unroll
        for (int j = 0; j < 8; j++) accp[p][j] = 0ull;

    for (int k0 = 0; k0 < K; k0 += GBK) {
        float4 av = *(const float4*)(Aptr + k0);
        float4 wv = *(const float4*)(Wptr + k0);
        As[(lk + 0) * SAP + lr] = av.x;
        As[(lk + 1) * SAP + lr] = av.y;
        As[(lk + 2) * SAP + lr] = av.z;
        As[(lk + 3) * SAP + lr] = av.w;
        Bs[(lk + 0) * SAP + lr] = wv.x;
        Bs[(lk + 1) * SAP + lr] = wv.y;
        Bs[(lk + 2) * SAP + lr] = wv.z;
        Bs[(lk + 3) * SAP + lr] = wv.w;
        __syncthreads();

        #pragma unroll
        for (int kk = 0; kk < GBK; kk++) {
            const float* abase = &As[kk * SAP + ty * 8];
            ulonglong2 a01 = *(const ulonglong2*)abase;
            ulonglong2 a23 = *(const ulonglong2*)(abase + 4);
            ull ap[4] = {a01.x, a01.y, a23.x, a23.y};

            const float* bbase = &Bs[kk * SAP + tx * 8];
            float4 bv0 = *(const float4*)bbase;
            float4 bv1 = *(const float4*)(bbase + 4);
            ull bsp[8] = {
                splat2(bv0.x), splat2(bv0.y), splat2(bv0.z), splat2(bv0.w),
                splat2(bv1.x), splat2(bv1.y), splat2(bv1.z), splat2(bv1.w)};

            #pragma unroll
            for (int p = 0; p < 4; p++)
                #pragma unroll
                for (int j = 0; j < 8; j++)
                    ffma2(accp[p][j], ap[p], bsp[j]);
        }
        __syncthreads();
    }

    float bs[8];
    #pragma unroll
    for (int j = 0; j < 8; j++) {
        int c = bcol + tx * 8 + j;
        bs[j] = __ldg(b1 + c) + __ldg(b2 + c);
    }

    #pragma unroll
    for (int p = 0; p < 4; p++) {
        float2 u[8];
        #pragma unroll
        for (int j = 0; j < 8; j++) u[j] = unpack2(accp[p][j]);

        int row0 = brow + ty * 8 + 2 * p;
        float* cp0 = C + (size_t)row0 * HDIM + bcol + tx * 8;
        float* cp1 = cp0 + HDIM;
        float4 o;
        o.x = u[0].x + bs[0]; o.y = u[1].x + bs[1];
        o.z = u[2].x + bs[2]; o.w = u[3].x + bs[3];
        *(float4*)(cp0) = o;
        o.x = u[4].x + bs[4]; o.y = u[5].x + bs[5];
        o.z = u[6].x + bs[6]; o.w = u[7].x + bs[7];
        *(float4*)(cp0 + 4) = o;
        o.x = u[0].y + bs[0]; o.y = u[1].y + bs[1];
        o.z = u[2].y + bs[2]; o.w = u[3].y + bs[3];
        *(float4*)(cp1) = o;
        o.x = u[4].y + bs[4]; o.y = u[5].y + bs[5];
        o.z = u[6].y + bs[6]; o.w = u[7].y + bs[7];
        *(float4*)(cp1 + 4) = o;
    }
}

// ---------------- batch-pipelined recurrence ----------------
// 128 CTAs x 256 threads. CTA cb owns cols [8cb, 8cb+8). Step t = 4 substeps,
// substep sg covers global batches [8sg, 8sg+8). Dependency distance is 4
// substeps, so publish->consume latency is hidden by other batch groups.
// Thread (bh=tid&1, ks=tid>>1): batches 4bh..4bh+3, k in [8ks, 8ks+8).
// W held in registers packed (k,k+1): Wr[c][k2] (32 ull). h pairs read once
// per CTA from the L2-resident g_hp ping-pong buffer (8x LDG.128/thread).
// 128-way k-split partials pre-collapsed to floats, reduced via 32KB
// XOR-swizzled smem + 4-lane shfl tree. Flags: [bg][cb], value t+1.
__global__ __launch_bounds__(256) void recur5(
    const float* __restrict__ xw,   // [t*B+b, H] input projection (+biases)
    const float* __restrict__ Whh,  // [H, H]
    float* __restrict__ hio,        // layer0: g_h1 [t,b,h] ; layer1: d_out [b,t,h]
    unsigned* __restrict__ flags,   // 4*128 flags
    int bth)
{
    // 256 threads x 16 slots x 8B = 32KB (slot index up to 4095)
    __shared__ __align__(16) char Psm[32768];

    int tid = threadIdx.x;
    int cb  = blockIdx.x;
    int bh  = tid & 1;
    int ks  = tid >> 1;             // 0..127

    // reducer coords (tid < 128): r = 4*o + q
    int o    = tid >> 2;            // 0..31 output pair
    int q    = tid & 3;
    int c2   = o & 3;               // col pair {2c2, 2c2+1}
    int b8   = o >> 2;              // 0..7 local batch
    int bh_p = b8 >> 2;
    int i_p  = c2 * 4 + (b8 & 3);

    // ---- load W into registers, packed (k, k+1): Wr[c*4 + k2] ----
    ull Wr[32];
    #pragma unroll
    for (int c = 0; c < 8; c++) {
        const char* wp = (const char*)(Whh + (size_t)(cb * 8 + c) * HDIM + 8 * ks);
        ulonglong2 w01 = *(const ulonglong2*)wp;
        ulonglong2 w23 = *(const ulonglong2*)(wp + 16);
        Wr[c * 4 + 0] = w01.x;
        Wr[c * 4 + 1] = w01.y;
        Wr[c * 4 + 2] = w23.x;
        Wr[c * 4 + 3] = w23.y;
    }

    for (int t = 0; t < TDIM; t++) {
        #pragma unroll 1
        for (int sg = 0; sg < 4; sg++) {
            // final-thread xw prefetch (independent of h)
            float2 xv = make_float2(0.f, 0.f);
            if (tid < 128 && q == 0) {
                xv = *(const float2*)(xw + ((size_t)t * BDIM + 8 * sg + b8) * HDIM
                                      + cb * 8 + 2 * c2);
            }

            if (t > 0) {
                // wait for all 128 producers of this batch group at step t-1
                if (tid < 128) {
                    unsigned f;
                    const unsigned* fp = flags + sg * 128 + tid;
                    do {
                        asm volatile("ld.acquire.gpu.u32 %0, [%1];"
                                     : "=r"(f) : "l"(fp));
                    } while (f < (unsigned)t);
                }
                __syncthreads();

                // ---- compute: h pairs direct from g_hp (read-once per CTA) ----
                const char* hbase = (const char*)(g_hp
                    + ((size_t)(sg * 2 + ((t - 1) & 1)) * 8 + 4 * bh) * HDIM
                    + 8 * ks);

                ull hreg[4][4];
                #pragma unroll
                for (int bb = 0; bb < 4; bb++) {
                    ulonglong2 h01 = ldcg16(hbase + bb * (HDIM * 4));
                    ulonglong2 h23 = ldcg16(hbase + bb * (HDIM * 4) + 16);
                    hreg[bb][0] = h01.x;
                    hreg[bb][1] = h01.y;
                    hreg[bb][2] = h23.x;
                    hreg[bb][3] = h23.y;
                }

                ull acc[8][4];
                #pragma unroll
                for (int c = 0; c < 8; c++)
                    #pragma unroll
                    for (int bb = 0; bb < 4; bb++) acc[c][bb] = 0ull;

                #pragma unroll
                for (int k2 = 0; k2 < 4; k2++)
                    #pragma unroll
                    for (int c = 0; c < 8; c++)
                        #pragma unroll
                        for (int bb = 0; bb < 4; bb++)
                            ffma2(acc[c][bb], hreg[bb][k2], Wr[c * 4 + k2]);

                // collapse k-lane pairs, pack col pairs, store partials
                float s[8][4];
                #pragma unroll
                for (int c = 0; c < 8; c++)
                    #pragma unroll
                    for (int bb = 0; bb < 4; bb++) {
                        float2 u = unpack2(acc[c][bb]);
                        s[c][bb] = u.x + u.y;
                    }
                #pragma unroll
                for (int cp = 0; cp < 4; cp++)
                    #pragma unroll
                    for (int bb = 0; bb < 4; bb++) {
                        int i    = cp * 4 + bb;
                        int slot = tid * 16 + (i ^ (tid & 15));
                        *(ull*)(Psm + slot * 8) = pack2(s[2 * cp][bb], s[2 * cp + 1][bb]);
                    }
            }
            __syncthreads();   // partials visible (or just a phase gate at t==0)

            if (tid < 128) {
                ull red = 0ull;
                if (t > 0) {
                    #pragma unroll 8
                    for (int m = 0; m < 32; m++) {
                        int tp   = bh_p + 2 * (q + 4 * m);
                        int slot = tp * 16 + (i_p ^ (tp & 15));
                        add2(red, *(const ull*)(Psm + slot * 8));
                    }
                    // combine the 4 q-lanes
                    ull r1 = __shfl_xor_sync(0xffffffffu, red, 1);
                    add2(red, r1);
                    ull r2 = __shfl_xor_sync(0xffffffffu, red, 2);
                    add2(red, r2);
                }
                if (q == 0) {
                    float2 u  = (t > 0) ? unpack2(red) : make_float2(0.f, 0.f);
                    float h0  = tanhf(xv.x + u.x);
                    float h1  = tanhf(xv.y + u.y);
                    int   gb   = 8 * sg + b8;
                    int   gcol = cb * 8 + 2 * c2;
                    size_t d = bth ? ((size_t)gb * TDIM + t) * HDIM + gcol
                                   : ((size_t)t * BDIM + gb) * HDIM + gcol;
                    *(float2*)(hio + d) = make_float2(h0, h1);
                    // publish to exchange buffer (parity t&1)
                    float* hp = g_hp + ((size_t)(sg * 2 + (t & 1)) * 8 + b8) * HDIM + gcol;
                    *(float2*)hp = make_float2(h0, h1);
                }
            }
            __syncthreads();   // all publishes done
            if (tid == 0) {
                asm volatile("st.release.gpu.u32 [%0], %1;"
                             :: "l"(flags + sg * 128 + cb), "r"((unsigned)(t + 1)));
            }
        }
    }
}

// ---------------- launch ----------------
extern "C" void kernel_launch(void* const* d_in, const int* in_sizes, int n_in,
                              void* d_out, int out_size)
{
    const float* x    = (const float*)d_in[0];
    const float* Wih0 = (const float*)d_in[1];
    const float* Whh0 = (const float*)d_in[2];
    const float* bih0 = (const float*)d_in[3];
    const float* bhh0 = (const float*)d_in[4];
    const float* Wih1 = (const float*)d_in[5];
    const float* Whh1 = (const float*)d_in[6];
    const float* bih1 = (const float*)d_in[7];
    const float* bhh1 = (const float*)d_in[8];
    float* out = (float*)d_out;

    float *xT, *xw, *h1;
    unsigned *f0, *f1;
    cudaGetSymbolAddress((void**)&xT, g_xT);
    cudaGetSymbolAddress((void**)&xw, g_xw);
    cudaGetSymbolAddress((void**)&h1, g_h1);
    cudaGetSymbolAddress((void**)&f0, g_flags0);
    cudaGetSymbolAddress((void**)&f1, g_flags1);

    init_flags<<<2, 256>>>();
    transpose_x<<<MDIM, 128>>>(x);
    gemm_bias<<<dim3(HDIM / 128, MDIM / 128), 256>>>(xT, Wih0, bih0, bhh0, xw, IDIM);
    recur5<<<128, 256>>>(xw, Whh0, h1, f0, 0);
    gemm_bias<<<dim3(HDIM / 128, MDIM / 128), 256>>>(h1, Wih1, bih1, bhh1, xw, HDIM);
    recur5<<<128, 256>>>(xw, Whh1, out, f1, 1);
}

// round 8
// speedup vs baseline: 1.4685x; 1.1933x over previous
#include <cuda_runtime.h>
#include <cuda_bf16.h>
#include <stdint.h>

typedef unsigned long long ull;

// Problem dims
#define BDIM 32
#define TDIM 512
#define IDIM 512
#define HDIM 1024
#define MDIM (TDIM * BDIM)   // 16384 rows (m = t*B + b)

// ---------------- scratch (static device globals; no allocation) ----------------
__device__ float g_xT[(size_t)MDIM * IDIM];   // x transposed to [t,b,i] rows
__device__ float g_xw[(size_t)MDIM * HDIM];   // xw0, later reused as xw1
__device__ float g_h1[(size_t)MDIM * HDIM];   // layer-0 hidden states [t,b,h]
__device__ float g_hp[8 * 2 * HDIM * 4];      // h exchange: [grp][parity][k][4 local b]

__device__ unsigned g_flags0[1024];           // [grp][cb]
__device__ unsigned g_flags1[1024];

// ---------------- f32x2 helpers ----------------
__device__ __forceinline__ void ffma2(ull& d, ull a, ull b) {
    asm("fma.rn.f32x2 %0, %1, %2, %0;" : "+l"(d) : "l"(a), "l"(b));
}
__device__ __forceinline__ void add2(ull& d, ull a) {
    asm("add.rn.f32x2 %0, %0, %1;" : "+l"(d) : "l"(a));
}
__device__ __forceinline__ ull splat2(float x) {
    ull r;
    asm("mov.b64 %0, {%1, %1};" : "=l"(r) : "f"(x));
    return r;
}
__device__ __forceinline__ float2 unpack2(ull v) {
    float lo, hi;
    asm("mov.b64 {%0, %1}, %2;" : "=f"(lo), "=f"(hi) : "l"(v));
    return make_float2(lo, hi);
}
__device__ __forceinline__ float4 ldcg_f4(const void* p) {
    float4 v;
    asm volatile("ld.global.cg.v4.f32 {%0,%1,%2,%3}, [%4];"
                 : "=f"(v.x), "=f"(v.y), "=f"(v.z), "=f"(v.w) : "l"(p));
    return v;
}

// ---------------- init flags (inside graph; replayed every run) ----------------
__global__ void init_flags() {
    int i = blockIdx.x * blockDim.x + threadIdx.x;
    if (i < 1024) {
        g_flags0[i] = 0;
        g_flags1[i] = 0;
    }
}

// ---------------- transpose x[B,T,I] -> xT[(t*B+b), I] ----------------
__global__ __launch_bounds__(128) void transpose_x(const float* __restrict__ x) {
    int m = blockIdx.x;
    int t = m >> 5;
    int b = m & 31;
    const float4* src = (const float4*)(x + ((size_t)b * TDIM + t) * IDIM);
    float4* dst = (float4*)(g_xT + (size_t)m * IDIM);
    dst[threadIdx.x] = src[threadIdx.x];
}

// ---------------- SGEMM: C[M,1024] = A[M,K] @ W[1024,K]^T + (b1+b2) ----------------
#define GBK 8
#define SAP 132

__global__ __launch_bounds__(256) void gemm_bias(
    const float* __restrict__ A, const float* __restrict__ W,
    const float* __restrict__ b1, const float* __restrict__ b2,
    float* __restrict__ C, int K)
{
    __shared__ __align__(16) float As[GBK * SAP];
    __shared__ __align__(16) float Bs[GBK * SAP];

    int tid  = threadIdx.x;
    int tx   = tid & 15;
    int ty   = tid >> 4;
    int brow = blockIdx.y * 128;
    int bcol = blockIdx.x * 128;

    int lr = tid >> 1;
    int lk = (tid & 1) * 4;

    const float* Aptr = A + (size_t)(brow + lr) * K + lk;
    const float* Wptr = W + (size_t)(bcol + lr) * K + lk;

    ull accp[4][8];
    #pragma unroll
    for (int p = 0; p < 4; p++)
        #pragma unroll
        for (int j = 0; j < 8; j++) accp[p][j] = 0ull;

    for (int k0 = 0; k0 < K; k0 += GBK) {
        float4 av = *(const float4*)(Aptr + k0);
        float4 wv = *(const float4*)(Wptr + k0);
        As[(lk + 0) * SAP + lr] = av.x;
        As[(lk + 1) * SAP + lr] = av.y;
        As[(lk + 2) * SAP + lr] = av.z;
        As[(lk + 3) * SAP + lr] = av.w;
        Bs[(lk + 0) * SAP + lr] = wv.x;
        Bs[(lk + 1) * SAP + lr] = wv.y;
        Bs[(lk + 2) * SAP + lr] = wv.z;
        Bs[(lk + 3) * SAP + lr] = wv.w;
        __syncthreads();

        #pragma unroll
        for (int kk = 0; kk < GBK; kk++) {
            const float* abase = &As[kk * SAP + ty * 8];
            ulonglong2 a01 = *(const ulonglong2*)abase;
            ulonglong2 a23 = *(const ulonglong2*)(abase + 4);
            ull ap[4] = {a01.x, a01.y, a23.x, a23.y};

            const float* bbase = &Bs[kk * SAP + tx * 8];
            float4 bv0 = *(const float4*)bbase;
            float4 bv1 = *(const float4*)(bbase + 4);
            ull bsp[8] = {
                splat2(bv0.x), splat2(bv0.y), splat2(bv0.z), splat2(bv0.w),
                splat2(bv1.x), splat2(bv1.y), splat2(bv1.z), splat2(bv1.w)};

            #pragma unroll
            for (int p = 0; p < 4; p++)
                #pragma unroll
                for (int j = 0; j < 8; j++)
                    ffma2(accp[p][j], ap[p], bsp[j]);
        }
        __syncthreads();
    }

    float bs[8];
    #pragma unroll
    for (int j = 0; j < 8; j++) {
        int c = bcol + tx * 8 + j;
        bs[j] = __ldg(b1 + c) + __ldg(b2 + c);
    }

    #pragma unroll
    for (int p = 0; p < 4; p++) {
        float2 u[8];
        #pragma unroll
        for (int j = 0; j < 8; j++) u[j] = unpack2(accp[p][j]);

        int row0 = brow + ty * 8 + 2 * p;
        float* cp0 = C + (size_t)row0 * HDIM + bcol + tx * 8;
        float* cp1 = cp0 + HDIM;
        float4 o;
        o.x = u[0].x + bs[0]; o.y = u[1].x + bs[1];
        o.z = u[2].x + bs[2]; o.w = u[3].x + bs[3];
        *(float4*)(cp0) = o;
        o.x = u[4].x + bs[4]; o.y = u[5].x + bs[5];
        o.z = u[6].x + bs[6]; o.w = u[7].x + bs[7];
        *(float4*)(cp0 + 4) = o;
        o.x = u[0].y + bs[0]; o.y = u[1].y + bs[1];
        o.z = u[2].y + bs[2]; o.w = u[3].y + bs[3];
        *(float4*)(cp1) = o;
        o.x = u[4].y + bs[4]; o.y = u[5].y + bs[5];
        o.z = u[6].y + bs[6]; o.w = u[7].y + bs[7];
        *(float4*)(cp1 + 4) = o;
    }
}

// ---------------- warp-per-group recurrence ----------------
// 128 CTAs x 256 threads. CTA cb owns cols [8cb, 8cb+8); all 8 warps share
// the CTA's W slice in smem (32KB, loaded once). Warp sg owns batch group
// [4sg, 4sg+4) and runs its own independent chain over t: poll 128 flags
// (4/lane) -> 32x LDG.128 of h[k][4b] -> 512 FFMA2 -> shfl butterfly
// reduction -> publish + lane0 release flag. No CTA barriers in the loop.
__global__ __launch_bounds__(256) void recur6(
    const float* __restrict__ xw,   // [t*B+b, H] input projection (+biases)
    const float* __restrict__ Whh,  // [H, H]
    float* __restrict__ hio,        // layer0: g_h1 [t,b,h] ; layer1: d_out [b,t,h]
    unsigned* __restrict__ flags,   // [grp][cb] = 8*128
    int bth)
{
    __shared__ __align__(16) float Wsm[8 * HDIM];   // [k][c], 32KB

    int tid  = threadIdx.x;
    int cb   = blockIdx.x;
    int lane = tid & 31;
    int sg   = tid >> 5;            // warp = batch group

    // Wsm[k*8 + c] = Whh[8cb + c][k]
    for (int idx = tid; idx < 8 * HDIM; idx += 256) {
        int c = idx >> 10;
        int k = idx & 1023;
        Wsm[k * 8 + c] = __ldg(Whh + (size_t)(cb * 8 + c) * HDIM + k);
    }
    __syncthreads();

    int half = (lane >> 2) & 1;     // bank de-conflict half selector
    // final output mapping after butterfly (lanes 16-31 duplicate 0-15)
    int cp_r = 2 * (lane & 1) + ((lane >> 1) & 1);   // col pair index 0..3
    int b_r  = 2 * ((lane >> 2) & 1) + ((lane >> 3) & 1);  // local batch 0..3
    int col0 = cb * 8 + 2 * cp_r;
    int gb   = sg * 4 + b_r;        // global batch

    const char* wbaseA = (const char*)Wsm + lane * 32 + half * 16;
    const char* wbaseB = (const char*)Wsm + lane * 32 + (1 - half) * 16;
    const unsigned* fpp = flags + sg * 128;

    for (int t = 0; t < TDIM; t++) {
        // xw load early (independent of h); lanes >=16 duplicate (broadcast)
        float2 xv = *(const float2*)(xw + ((size_t)t * BDIM + gb) * HDIM + col0);

        float h0, h1;
        if (t == 0) {
            h0 = tanhf(xv.x);
            h1 = tanhf(xv.y);
        } else {
            // ---- poll: all 128 producers of group sg at step t-1 ----
            unsigned tt = (unsigned)t;
            for (;;) {
                unsigned f0, f1, f2, f3;
                asm volatile("ld.acquire.gpu.u32 %0, [%1];" : "=r"(f0) : "l"(fpp + lane));
                asm volatile("ld.acquire.gpu.u32 %0, [%1];" : "=r"(f1) : "l"(fpp + lane + 32));
                asm volatile("ld.acquire.gpu.u32 %0, [%1];" : "=r"(f2) : "l"(fpp + lane + 64));
                asm volatile("ld.acquire.gpu.u32 %0, [%1];" : "=r"(f3) : "l"(fpp + lane + 96));
                bool ok = (f0 >= tt) & (f1 >= tt) & (f2 >= tt) & (f3 >= tt);
                if (__all_sync(0xffffffffu, ok)) break;
            }
            __syncwarp();

            // ---- compute: k = lane + 32m, m = 0..31, chunks of 8 ----
            const char* hbase = (const char*)g_hp
                + (size_t)(sg * 2 + ((t - 1) & 1)) * (HDIM * 4 * 4)
                + (size_t)lane * 16;

            ull accA0[4], accA1[4], accB0[4], accB1[4];
            #pragma unroll
            for (int b = 0; b < 4; b++) {
                accA0[b] = 0ull; accA1[b] = 0ull;
                accB0[b] = 0ull; accB1[b] = 0ull;
            }

            float4 hbuf[2][8];
            #pragma unroll
            for (int i = 0; i < 8; i++)
                hbuf[0][i] = ldcg_f4(hbase + i * 512);

            #pragma unroll
            for (int m = 0; m < 4; m++) {
                if (m < 3) {
                    #pragma unroll
                    for (int i = 0; i < 8; i++)
                        hbuf[(m + 1) & 1][i] = ldcg_f4(hbase + ((m + 1) * 8 + i) * 512);
                }
                #pragma unroll
                for (int i = 0; i < 8; i++) {
                    int koff = (m * 8 + i) * 1024;   // bytes: k stride 32 lanes * 32B
                    ulonglong2 wA = *(const ulonglong2*)(wbaseA + koff);
                    ulonglong2 wB = *(const ulonglong2*)(wbaseB + koff);
                    float4 h = hbuf[m & 1][i];
                    ull s0 = splat2(h.x), s1 = splat2(h.y);
                    ull s2 = splat2(h.z), s3 = splat2(h.w);
                    ffma2(accA0[0], s0, wA.x); ffma2(accA1[0], s0, wA.y);
                    ffma2(accB0[0], s0, wB.x); ffma2(accB1[0], s0, wB.y);
                    ffma2(accA0[1], s1, wA.x); ffma2(accA1[1], s1, wA.y);
                    ffma2(accB0[1], s1, wB.x); ffma2(accB1[1], s1, wB.y);
                    ffma2(accA0[2], s2, wA.x); ffma2(accA1[2], s2, wA.y);
                    ffma2(accB0[2], s2, wB.x); ffma2(accB1[2], s2, wB.y);
                    ffma2(accA0[3], s3, wA.x); ffma2(accA1[3], s3, wA.y);
                    ffma2(accB0[3], s3, wB.x); ffma2(accB1[3], s3, wB.y);
                }
            }

            // normalize to physical col-pair order: a[cp*4 + b]
            ull a[16];
            if (half == 0) {
                #pragma unroll
                for (int b = 0; b < 4; b++) {
                    a[0 + b] = accA0[b]; a[4 + b]  = accA1[b];
                    a[8 + b] = accB0[b]; a[12 + b] = accB1[b];
                }
            } else {
                #pragma unroll
                for (int b = 0; b < 4; b++) {
                    a[0 + b] = accB0[b]; a[4 + b]  = accB1[b];
                    a[8 + b] = accA0[b]; a[12 + b] = accA1[b];
                }
            }

            // butterfly reduction across 32 lanes
            #pragma unroll
            for (int i = 0; i < 16; i++) {
                ull r = __shfl_xor_sync(0xffffffffu, a[i], 16);
                add2(a[i], r);
            }
            {   // mask 1, keep 8
                int bit = lane & 1;
                #pragma unroll
                for (int i = 0; i < 8; i++) {
                    ull snd = bit ? a[i] : a[i + 8];
                    ull rcv = __shfl_xor_sync(0xffffffffu, snd, 1);
                    a[i] = bit ? a[i + 8] : a[i];
                    add2(a[i], rcv);
                }
            }
            {   // mask 2, keep 4
                int bit = (lane >> 1) & 1;
                #pragma unroll
                for (int i = 0; i < 4; i++) {
                    ull snd = bit ? a[i] : a[i + 4];
                    ull rcv = __shfl_xor_sync(0xffffffffu, snd, 2);
                    a[i] = bit ? a[i + 4] : a[i];
                    add2(a[i], rcv);
                }
            }
            {   // mask 4, keep 2
                int bit = (lane >> 2) & 1;
                #pragma unroll
                for (int i = 0; i < 2; i++) {
                    ull snd = bit ? a[i] : a[i + 2];
                    ull rcv = __shfl_xor_sync(0xffffffffu, snd, 4);
                    a[i] = bit ? a[i + 2] : a[i];
                    add2(a[i], rcv);
                }
            }
            {   // mask 8, keep 1
                int bit = (lane >> 3) & 1;
                ull snd = bit ? a[0] : a[1];
                ull rcv = __shfl_xor_sync(0xffffffffu, snd, 8);
                a[0] = bit ? a[1] : a[0];
                add2(a[0], rcv);
            }

            float2 u = unpack2(a[0]);
            h0 = tanhf(xv.x + u.x);
            h1 = tanhf(xv.y + u.y);
        }

        if (lane < 16) {
            size_t d = bth ? ((size_t)gb * TDIM + t) * HDIM + col0
                           : ((size_t)t * BDIM + gb) * HDIM + col0;
            *(float2*)(hio + d) = make_float2(h0, h1);

            float* pb = g_hp + (size_t)(sg * 2 + (t & 1)) * (HDIM * 4);
            pb[(col0 + 0) * 4 + b_r] = h0;
            pb[(col0 + 1) * 4 + b_r] = h1;
        }

        __syncwarp();
        if (lane == 0) {
            asm volatile("st.release.gpu.u32 [%0], %1;"
                         :: "l"(flags + sg * 128 + cb), "r"((unsigned)(t + 1)));
        }
    }
}

// ---------------- launch ----------------
extern "C" void kernel_launch(void* const* d_in, const int* in_sizes, int n_in,
                              void* d_out, int out_size)
{
    const float* x    = (const float*)d_in[0];
    const float* Wih0 = (const float*)d_in[1];
    const float* Whh0 = (const float*)d_in[2];
    const float* bih0 = (const float*)d_in[3];
    const float* bhh0 = (const float*)d_in[4];
    const float* Wih1 = (const float*)d_in[5];
    const float* Whh1 = (const float*)d_in[6];
    const float* bih1 = (const float*)d_in[7];
    const float* bhh1 = (const float*)d_in[8];
    float* out = (float*)d_out;

    float *xT, *xw, *h1;
    unsigned *f0, *f1;
    cudaGetSymbolAddress((void**)&xT, g_xT);
    cudaGetSymbolAddress((void**)&xw, g_xw);
    cudaGetSymbolAddress((void**)&h1, g_h1);
    cudaGetSymbolAddress((void**)&f0, g_flags0);
    cudaGetSymbolAddress((void**)&f1, g_flags1);

    init_flags<<<4, 256>>>();
    transpose_x<<<MDIM, 128>>>(x);
    gemm_bias<<<dim3(HDIM / 128, MDIM / 128), 256>>>(xT, Wih0, bih0, bhh0, xw, IDIM);
    recur6<<<128, 256>>>(xw, Whh0, h1, f0, 0);
    gemm_bias<<<dim3(HDIM / 128, MDIM / 128), 256>>>(h1, Wih1, bih1, bhh1, xw, HDIM);
    recur6<<<128, 256>>>(xw, Whh1, out, f1, 1);
}

// round 9
// speedup vs baseline: 2.1003x; 1.4302x over previous
#include <cuda_runtime.h>
#include <cuda_bf16.h>
#include <stdint.h>

typedef unsigned long long ull;

// Problem dims
#define BDIM 32
#define TDIM 512
#define IDIM 512
#define HDIM 1024
#define MDIM (TDIM * BDIM)   // 16384 rows (m = t*B + b)

// ---------------- scratch (static device globals; no allocation) ----------------
__device__ float g_xT[(size_t)MDIM * IDIM];   // x transposed to [t,b,i] rows
__device__ float g_xw[(size_t)MDIM * HDIM];   // xw0 (layer-0 input projection)
__device__ float g_hp1[8][4][HDIM * 4];       // h1 ring: [grp][slot][k][4 local b]
__device__ float g_hp2[8][4][HDIM * 4];       // h2 ring

__device__ unsigned g_fh1[1024];              // [grp][cb] layer-0 progress
__device__ unsigned g_fh2[1024];              // layer-1 progress

// ---------------- f32x2 helpers ----------------
__device__ __forceinline__ void ffma2(ull& d, ull a, ull b) {
    asm("fma.rn.f32x2 %0, %1, %2, %0;" : "+l"(d) : "l"(a), "l"(b));
}
__device__ __forceinline__ void add2(ull& d, ull a) {
    asm("add.rn.f32x2 %0, %0, %1;" : "+l"(d) : "l"(a));
}
__device__ __forceinline__ ull splat2(float x) {
    ull r;
    asm("mov.b64 %0, {%1, %1};" : "=l"(r) : "f"(x));
    return r;
}
__device__ __forceinline__ float2 unpack2(ull v) {
    float lo, hi;
    asm("mov.b64 {%0, %1}, %2;" : "=f"(lo), "=f"(hi) : "l"(v));
    return make_float2(lo, hi);
}
__device__ __forceinline__ float4 ldcg_f4(const void* p) {
    float4 v;
    asm volatile("ld.global.cg.v4.f32 {%0,%1,%2,%3}, [%4];"
                 : "=f"(v.x), "=f"(v.y), "=f"(v.z), "=f"(v.w) : "l"(p));
    return v;
}

// ---------------- init flags (inside graph; replayed every run) ----------------
__global__ void init_flags() {
    int i = blockIdx.x * blockDim.x + threadIdx.x;
    if (i < 1024) {
        g_fh1[i] = 0;
        g_fh2[i] = 0;
    }
}

// ---------------- transpose x[B,T,I] -> xT[(t*B+b), I] ----------------
__global__ __launch_bounds__(128) void transpose_x(const float* __restrict__ x) {
    int m = blockIdx.x;
    int t = m >> 5;
    int b = m & 31;
    const float4* src = (const float4*)(x + ((size_t)b * TDIM + t) * IDIM);
    float4* dst = (float4*)(g_xT + (size_t)m * IDIM);
    dst[threadIdx.x] = src[threadIdx.x];
}

// ---------------- SGEMM (layer-0 input projection only) ----------------
#define GBK 8
#define SAP 132

__global__ __launch_bounds__(256) void gemm_bias(
    const float* __restrict__ A, const float* __restrict__ W,
    const float* __restrict__ b1, const float* __restrict__ b2,
    float* __restrict__ C, int K)
{
    __shared__ __align__(16) float As[GBK * SAP];
    __shared__ __align__(16) float Bs[GBK * SAP];

    int tid  = threadIdx.x;
    int tx   = tid & 15;
    int ty   = tid >> 4;
    int brow = blockIdx.y * 128;
    int bcol = blockIdx.x * 128;

    int lr = tid >> 1;
    int lk = (tid & 1) * 4;

    const float* Aptr = A + (size_t)(brow + lr) * K + lk;
    const float* Wptr = W + (size_t)(bcol + lr) * K + lk;

    ull accp[4][8];
    #pragma unroll
    for (int p = 0; p < 4; p++)
        #pragma unroll
        for (int j = 0; j < 8; j++) accp[p][j] = 0ull;

    for (int k0 = 0; k0 < K; k0 += GBK) {
        float4 av = *(const float4*)(Aptr + k0);
        float4 wv = *(const float4*)(Wptr + k0);
        As[(lk + 0) * SAP + lr] = av.x;
        As[(lk + 1) * SAP + lr] = av.y;
        As[(lk + 2) * SAP + lr] = av.z;
        As[(lk + 3) * SAP + lr] = av.w;
        Bs[(lk + 0) * SAP + lr] = wv.x;
        Bs[(lk + 1) * SAP + lr] = wv.y;
        Bs[(lk + 2) * SAP + lr] = wv.z;
        Bs[(lk + 3) * SAP + lr] = wv.w;
        __syncthreads();

        #pragma unroll
        for (int kk = 0; kk < GBK; kk++) {
            const float* abase = &As[kk * SAP + ty * 8];
            ulonglong2 a01 = *(const ulonglong2*)abase;
            ulonglong2 a23 = *(const ulonglong2*)(abase + 4);
            ull ap[4] = {a01.x, a01.y, a23.x, a23.y};

            const float* bbase = &Bs[kk * SAP + tx * 8];
            float4 bv0 = *(const float4*)bbase;
            float4 bv1 = *(const float4*)(bbase + 4);
            ull bsp[8] = {
                splat2(bv0.x), splat2(bv0.y), splat2(bv0.z), splat2(bv0.w),
                splat2(bv1.x), splat2(bv1.y), splat2(bv1.z), splat2(bv1.w)};

            #pragma unroll
            for (int p = 0; p < 4; p++)
                #pragma unroll
                for (int j = 0; j < 8; j++)
                    ffma2(accp[p][j], ap[p], bsp[j]);
        }
        __syncthreads();
    }

    float bs[8];
    #pragma unroll
    for (int j = 0; j < 8; j++) {
        int c = bcol + tx * 8 + j;
        bs[j] = __ldg(b1 + c) + __ldg(b2 + c);
    }

    #pragma unroll
    for (int p = 0; p < 4; p++) {
        float2 u[8];
        #pragma unroll
        for (int j = 0; j < 8; j++) u[j] = unpack2(accp[p][j]);

        int row0 = brow + ty * 8 + 2 * p;
        float* cp0 = C + (size_t)row0 * HDIM + bcol + tx * 8;
        float* cp1 = cp0 + HDIM;
        float4 o;
        o.x = u[0].x + bs[0]; o.y = u[1].x + bs[1];
        o.z = u[2].x + bs[2]; o.w = u[3].x + bs[3];
        *(float4*)(cp0) = o;
        o.x = u[4].x + bs[4]; o.y = u[5].x + bs[5];
        o.z = u[6].x + bs[6]; o.w = u[7].x + bs[7];
        *(float4*)(cp0 + 4) = o;
        o.x = u[0].y + bs[0]; o.y = u[1].y + bs[1];
        o.z = u[2].y + bs[2]; o.w = u[3].y + bs[3];
        *(float4*)(cp1) = o;
        o.x = u[4].y + bs[4]; o.y = u[5].y + bs[5];
        o.z = u[6].y + bs[6]; o.w = u[7].y + bs[7];
        *(float4*)(cp1 + 4) = o;
    }
}

// ---------------- fused 2-layer pipelined recurrence ----------------
// 128 CTAs x 256 threads; CTA cb owns cols [8cb,8cb+8) of BOTH layers.
// Warp sg owns batch group [4sg,4sg+4). Iteration i (0..512):
//   A (i<512): h1(i) = tanh(xw0(i) + Whh0 . h1(i-1)); publish to h1 ring.
//   B (i>=1): s=i-1; z = Wih1 . h1(s) + b; h2(s) = tanh(z + Whh1 . h2(s-1));
//             write d_out, publish to h2 ring.
// 4-slot rings; per-group per-CTA flags; no CTA barriers in the loop.
#define FU_SMEM_BYTES (3 * 8 * HDIM * 4)   // 96KB: Wh0, Wi1, Wh1 slices [k][8c]

// warp-wide 1024-long dot for 8 cols x 4 batches; returns reduced pair for
// this lane's (cp_r, b_r) assignment (lanes 16-31 duplicate 0-15).
__device__ __forceinline__ ull dot_block(const float* __restrict__ Wsm,
                                         const char* __restrict__ hbase,
                                         int lane, int half) {
    const char* wbaseA = (const char*)Wsm + lane * 32 + half * 16;
    const char* wbaseB = (const char*)Wsm + lane * 32 + (1 - half) * 16;

    ull accA0[4], accA1[4], accB0[4], accB1[4];
    #pragma unroll
    for (int b = 0; b < 4; b++) {
        accA0[b] = 0ull; accA1[b] = 0ull;
        accB0[b] = 0ull; accB1[b] = 0ull;
    }

    float4 hbuf[2][8];
    #pragma unroll
    for (int i = 0; i < 8; i++)
        hbuf[0][i] = ldcg_f4(hbase + i * 512);

    #pragma unroll
    for (int m = 0; m < 4; m++) {
        if (m < 3) {
            #pragma unroll
            for (int i = 0; i < 8; i++)
                hbuf[(m + 1) & 1][i] = ldcg_f4(hbase + ((m + 1) * 8 + i) * 512);
        }
        #pragma unroll
        for (int i = 0; i < 8; i++) {
            int koff = (m * 8 + i) * 1024;
            ulonglong2 wA = *(const ulonglong2*)(wbaseA + koff);
            ulonglong2 wB = *(const ulonglong2*)(wbaseB + koff);
            float4 h = hbuf[m & 1][i];
            ull s0 = splat2(h.x), s1 = splat2(h.y);
            ull s2 = splat2(h.z), s3 = splat2(h.w);
            ffma2(accA0[0], s0, wA.x); ffma2(accA1[0], s0, wA.y);
            ffma2(accB0[0], s0, wB.x); ffma2(accB1[0], s0, wB.y);
            ffma2(accA0[1], s1, wA.x); ffma2(accA1[1], s1, wA.y);
            ffma2(accB0[1], s1, wB.x); ffma2(accB1[1], s1, wB.y);
            ffma2(accA0[2], s2, wA.x); ffma2(accA1[2], s2, wA.y);
            ffma2(accB0[2], s2, wB.x); ffma2(accB1[2], s2, wB.y);
            ffma2(accA0[3], s3, wA.x); ffma2(accA1[3], s3, wA.y);
            ffma2(accB0[3], s3, wB.x); ffma2(accB1[3], s3, wB.y);
        }
    }

    // normalize to physical col-pair order: a[cp*4 + b]
    ull a[16];
    if (half == 0) {
        #pragma unroll
        for (int b = 0; b < 4; b++) {
            a[0 + b] = accA0[b]; a[4 + b]  = accA1[b];
            a[8 + b] = accB0[b]; a[12 + b] = accB1[b];
        }
    } else {
        #pragma unroll
        for (int b = 0; b < 4; b++) {
            a[0 + b] = accB0[b]; a[4 + b]  = accB1[b];
            a[8 + b] = accA0[b]; a[12 + b] = accA1[b];
        }
    }

    // butterfly reduction across 32 lanes
    #pragma unroll
    for (int i = 0; i < 16; i++) {
        ull r = __shfl_xor_sync(0xffffffffu, a[i], 16);
        add2(a[i], r);
    }
    {
        int bit = lane & 1;
        #pragma unroll
        for (int i = 0; i < 8; i++) {
            ull snd = bit ? a[i] : a[i + 8];
            ull rcv = __shfl_xor_sync(0xffffffffu, snd, 1);
            a[i] = bit ? a[i + 8] : a[i];
            add2(a[i], rcv);
        }
    }
    {
        int bit = (lane >> 1) & 1;
        #pragma unroll
        for (int i = 0; i < 4; i++) {
            ull snd = bit ? a[i] : a[i + 4];
            ull rcv = __shfl_xor_sync(0xffffffffu, snd, 2);
            a[i] = bit ? a[i + 4] : a[i];
            add2(a[i], rcv);
        }
    }
    {
        int bit = (lane >> 2) & 1;
        #pragma unroll
        for (int i = 0; i < 2; i++) {
            ull snd = bit ? a[i] : a[i + 2];
            ull rcv = __shfl_xor_sync(0xffffffffu, snd, 4);
            a[i] = bit ? a[i + 2] : a[i];
            add2(a[i], rcv);
        }
    }
    {
        int bit = (lane >> 3) & 1;
        ull snd = bit ? a[0] : a[1];
        ull rcv = __shfl_xor_sync(0xffffffffu, snd, 8);
        a[0] = bit ? a[1] : a[0];
        add2(a[0], rcv);
    }
    return a[0];
}

__device__ __forceinline__ void poll_all(const unsigned* __restrict__ fpp,
                                         unsigned tt, int lane) {
    for (;;) {
        unsigned f0, f1, f2, f3;
        asm volatile("ld.acquire.gpu.u32 %0, [%1];" : "=r"(f0) : "l"(fpp + lane));
        asm volatile("ld.acquire.gpu.u32 %0, [%1];" : "=r"(f1) : "l"(fpp + lane + 32));
        asm volatile("ld.acquire.gpu.u32 %0, [%1];" : "=r"(f2) : "l"(fpp + lane + 64));
        asm volatile("ld.acquire.gpu.u32 %0, [%1];" : "=r"(f3) : "l"(fpp + lane + 96));
        bool ok = (f0 >= tt) & (f1 >= tt) & (f2 >= tt) & (f3 >= tt);
        if (__all_sync(0xffffffffu, ok)) break;
    }
}

__global__ __launch_bounds__(256) void recur_fused(
    const float* __restrict__ xw0,   // [i*B+b, H] layer-0 input projection
    const float* __restrict__ Whh0,
    const float* __restrict__ Wih1,
    const float* __restrict__ Whh1,
    const float* __restrict__ bih1,
    const float* __restrict__ bhh1,
    float* __restrict__ out)         // [B, T, H]
{
    extern __shared__ __align__(16) float sm[];
    float* Wh0 = sm;                 // [k][8c]
    float* Wi1 = sm + 8 * HDIM;
    float* Wh1 = sm + 16 * HDIM;

    int tid  = threadIdx.x;
    int cb   = blockIdx.x;
    int lane = tid & 31;
    int sg   = tid >> 5;

    // load the three 8-col weight slices, [k][c] layout
    for (int idx = tid; idx < 8 * HDIM; idx += 256) {
        int c = idx >> 10;
        int k = idx & 1023;
        Wh0[k * 8 + c] = __ldg(Whh0 + (size_t)(cb * 8 + c) * HDIM + k);
        Wi1[k * 8 + c] = __ldg(Wih1 + (size_t)(cb * 8 + c) * HDIM + k);
        Wh1[k * 8 + c] = __ldg(Whh1 + (size_t)(cb * 8 + c) * HDIM + k);
    }
    __syncthreads();

    int half = (lane >> 2) & 1;
    int cp_r = 2 * (lane & 1) + ((lane >> 1) & 1);
    int b_r  = 2 * ((lane >> 2) & 1) + ((lane >> 3) & 1);
    int col0 = cb * 8 + 2 * cp_r;
    int gb   = sg * 4 + b_r;

    const unsigned* fpp1 = g_fh1 + sg * 128;
    const unsigned* fpp2 = g_fh2 + sg * 128;
    unsigned* myf1 = g_fh1 + sg * 128 + cb;
    unsigned* myf2 = g_fh2 + sg * 128 + cb;

    float2 bsum;
    bsum.x = __ldg(bih1 + col0) + __ldg(bhh1 + col0);
    bsum.y = __ldg(bih1 + col0 + 1) + __ldg(bhh1 + col0 + 1);

    for (int i = 0; i <= TDIM; i++) {
        // one poll gates both h1(i-1) uses (A's recurrent read, B's z read)
        if (i > 0) poll_all(fpp1, (unsigned)i, lane);

        // ---- part A: h1(i) ----
        if (i < TDIM) {
            float2 xv = *(const float2*)(xw0 + ((size_t)i * BDIM + gb) * HDIM + col0);
            float v0, v1;
            if (i == 0) {
                v0 = tanhf(xv.x);
                v1 = tanhf(xv.y);
            } else {
                const char* hb = (const char*)&g_hp1[sg][(i - 1) & 3][0] + lane * 16;
                float2 u = unpack2(dot_block(Wh0, hb, lane, half));
                v0 = tanhf(xv.x + u.x);
                v1 = tanhf(xv.y + u.y);
            }
            if (lane < 16) {
                float* pb = &g_hp1[sg][i & 3][0];
                pb[(col0 + 0) * 4 + b_r] = v0;
                pb[(col0 + 1) * 4 + b_r] = v1;
            }
            __syncwarp();
            if (lane == 0) {
                asm volatile("st.release.gpu.u32 [%0], %1;"
                             :: "l"(myf1), "r"((unsigned)(i + 1)));
            }
        }

        // ---- part B: z(s), h2(s) for s = i-1 ----
        if (i > 0) {
            int s = i - 1;
            const char* hb1 = (const char*)&g_hp1[sg][s & 3][0] + lane * 16;
            float2 uz = unpack2(dot_block(Wi1, hb1, lane, half));
            float o0 = bsum.x + uz.x;
            float o1 = bsum.y + uz.y;

            if (s > 0) {
                poll_all(fpp2, (unsigned)s, lane);
                const char* hb2 = (const char*)&g_hp2[sg][(s - 1) & 3][0] + lane * 16;
                float2 ur = unpack2(dot_block(Wh1, hb2, lane, half));
                o0 += ur.x;
                o1 += ur.y;
            }
            float v0 = tanhf(o0);
            float v1 = tanhf(o1);

            if (lane < 16) {
                *(float2*)(out + ((size_t)gb * TDIM + s) * HDIM + col0)
                    = make_float2(v0, v1);
                float* pb = &g_hp2[sg][s & 3][0];
                pb[(col0 + 0) * 4 + b_r] = v0;
                pb[(col0 + 1) * 4 + b_r] = v1;
            }
            __syncwarp();
            if (lane == 0) {
                asm volatile("st.release.gpu.u32 [%0], %1;"
                             :: "l"(myf2), "r"((unsigned)(s + 1)));
            }
        }
    }
}

// ---------------- launch ----------------
extern "C" void kernel_launch(void* const* d_in, const int* in_sizes, int n_in,
                              void* d_out, int out_size)
{
    const float* x    = (const float*)d_in[0];
    const float* Wih0 = (const float*)d_in[1];
    const float* Whh0 = (const float*)d_in[2];
    const float* bih0 = (const float*)d_in[3];
    const float* bhh0 = (const float*)d_in[4];
    const float* Wih1 = (const float*)d_in[5];
    const float* Whh1 = (const float*)d_in[6];
    const float* bih1 = (const float*)d_in[7];
    const float* bhh1 = (const float*)d_in[8];
    float* out = (float*)d_out;

    float *xT, *xw;
    cudaGetSymbolAddress((void**)&xT, g_xT);
    cudaGetSymbolAddress((void**)&xw, g_xw);

    cudaFuncSetAttribute(recur_fused, cudaFuncAttributeMaxDynamicSharedMemorySize,
                         FU_SMEM_BYTES);

    init_flags<<<4, 256>>>();
    transpose_x<<<MDIM, 128>>>(x);
    gemm_bias<<<dim3(HDIM / 128, MDIM / 128), 256>>>(xT, Wih0, bih0, bhh0, xw, IDIM);
    recur_fused<<<128, 256, FU_SMEM_BYTES>>>(xw, Whh0, Wih1, Whh1, bih1, bhh1, out);
}

// round 10
// speedup vs baseline: 2.6460x; 1.2599x over previous
#include <cuda_runtime.h>
#include <cuda_bf16.h>
#include <stdint.h>

typedef unsigned long long ull;

// Problem dims
#define BDIM 32
#define TDIM 512
#define IDIM 512
#define HDIM 1024
#define MDIM (TDIM * BDIM)   // 16384 rows (m = t*B + b)

// ---------------- scratch (static device globals; no allocation) ----------------
__device__ float g_xT[(size_t)MDIM * IDIM];   // x transposed to [t,b,i] rows
__device__ float g_xw[(size_t)MDIM * HDIM];   // xw0 (layer-0 input projection)
__device__ float g_hp1[8][4][HDIM * 4];       // h1 ring: [grp][slot][k][4 local b]
__device__ float g_hp2[8][4][HDIM * 4];       // h2 ring

__device__ unsigned g_fh1[1024];              // [grp][cb] layer-0 progress
__device__ unsigned g_fh2[1024];              // layer-1 progress

// ---------------- f32x2 helpers ----------------
__device__ __forceinline__ void ffma2(ull& d, ull a, ull b) {
    asm("fma.rn.f32x2 %0, %1, %2, %0;" : "+l"(d) : "l"(a), "l"(b));
}
__device__ __forceinline__ void add2(ull& d, ull a) {
    asm("add.rn.f32x2 %0, %0, %1;" : "+l"(d) : "l"(a));
}
__device__ __forceinline__ ull splat2(float x) {
    ull r;
    asm("mov.b64 %0, {%1, %1};" : "=l"(r) : "f"(x));
    return r;
}
__device__ __forceinline__ float2 unpack2(ull v) {
    float lo, hi;
    asm("mov.b64 {%0, %1}, %2;" : "=f"(lo), "=f"(hi) : "l"(v));
    return make_float2(lo, hi);
}
__device__ __forceinline__ float4 ldcg_f4(const void* p) {
    float4 v;
    asm volatile("ld.global.cg.v4.f32 {%0,%1,%2,%3}, [%4];"
                 : "=f"(v.x), "=f"(v.y), "=f"(v.z), "=f"(v.w) : "l"(p));
    return v;
}

// ---------------- init flags (inside graph; replayed every run) ----------------
__global__ void init_flags() {
    int i = blockIdx.x * blockDim.x + threadIdx.x;
    if (i < 1024) {
        g_fh1[i] = 0;
        g_fh2[i] = 0;
    }
}

// ---------------- transpose x[B,T,I] -> xT[(t*B+b), I] ----------------
__global__ __launch_bounds__(128) void transpose_x(const float* __restrict__ x) {
    int m = blockIdx.x;
    int t = m >> 5;
    int b = m & 31;
    const float4* src = (const float4*)(x + ((size_t)b * TDIM + t) * IDIM);
    float4* dst = (float4*)(g_xT + (size_t)m * IDIM);
    dst[threadIdx.x] = src[threadIdx.x];
}

// ---------------- SGEMM (layer-0 input projection only) ----------------
#define GBK 8
#define SAP 132

__global__ __launch_bounds__(256) void gemm_bias(
    const float* __restrict__ A, const float* __restrict__ W,
    const float* __restrict__ b1, const float* __restrict__ b2,
    float* __restrict__ C, int K)
{
    __shared__ __align__(16) float As[GBK * SAP];
    __shared__ __align__(16) float Bs[GBK * SAP];

    int tid  = threadIdx.x;
    int tx   = tid & 15;
    int ty   = tid >> 4;
    int brow = blockIdx.y * 128;
    int bcol = blockIdx.x * 128;

    int lr = tid >> 1;
    int lk = (tid & 1) * 4;

    const float* Aptr = A + (size_t)(brow + lr) * K + lk;
    const float* Wptr = W + (size_t)(bcol + lr) * K + lk;

    ull accp[4][8];
    #pragma unroll
    for (int p = 0; p < 4; p++)
        #pragma unroll
        for (int j = 0; j < 8; j++) accp[p][j] = 0ull;

    for (int k0 = 0; k0 < K; k0 += GBK) {
        float4 av = *(const float4*)(Aptr + k0);
        float4 wv = *(const float4*)(Wptr + k0);
        As[(lk + 0) * SAP + lr] = av.x;
        As[(lk + 1) * SAP + lr] = av.y;
        As[(lk + 2) * SAP + lr] = av.z;
        As[(lk + 3) * SAP + lr] = av.w;
        Bs[(lk + 0) * SAP + lr] = wv.x;
        Bs[(lk + 1) * SAP + lr] = wv.y;
        Bs[(lk + 2) * SAP + lr] = wv.z;
        Bs[(lk + 3) * SAP + lr] = wv.w;
        __syncthreads();

        #pragma unroll
        for (int kk = 0; kk < GBK; kk++) {
            const float* abase = &As[kk * SAP + ty * 8];
            ulonglong2 a01 = *(const ulonglong2*)abase;
            ulonglong2 a23 = *(const ulonglong2*)(abase + 4);
            ull ap[4] = {a01.x, a01.y, a23.x, a23.y};

            const float* bbase = &Bs[kk * SAP + tx * 8];
            float4 bv0 = *(const float4*)bbase;
            float4 bv1 = *(const float4*)(bbase + 4);
            ull bsp[8] = {
                splat2(bv0.x), splat2(bv0.y), splat2(bv0.z), splat2(bv0.w),
                splat2(bv1.x), splat2(bv1.y), splat2(bv1.z), splat2(bv1.w)};

            #pragma unroll
            for (int p = 0; p < 4; p++)
                #pragma unroll
                for (int j = 0; j < 8; j++)
                    ffma2(accp[p][j], ap[p], bsp[j]);
        }
        __syncthreads();
    }

    float bs[8];
    #pragma unroll
    for (int j = 0; j < 8; j++) {
        int c = bcol + tx * 8 + j;
        bs[j] = __ldg(b1 + c) + __ldg(b2 + c);
    }

    #pragma unroll
    for (int p = 0; p < 4; p++) {
        float2 u[8];
        #pragma unroll
        for (int j = 0; j < 8; j++) u[j] = unpack2(accp[p][j]);

        int row0 = brow + ty * 8 + 2 * p;
        float* cp0 = C + (size_t)row0 * HDIM + bcol + tx * 8;
        float* cp1 = cp0 + HDIM;
        float4 o;
        o.x = u[0].x + bs[0]; o.y = u[1].x + bs[1];
        o.z = u[2].x + bs[2]; o.w = u[3].x + bs[3];
        *(float4*)(cp0) = o;
        o.x = u[4].x + bs[4]; o.y = u[5].x + bs[5];
        o.z = u[6].x + bs[6]; o.w = u[7].x + bs[7];
        *(float4*)(cp0 + 4) = o;
        o.x = u[0].y + bs[0]; o.y = u[1].y + bs[1];
        o.z = u[2].y + bs[2]; o.w = u[3].y + bs[3];
        *(float4*)(cp1) = o;
        o.x = u[4].y + bs[4]; o.y = u[5].y + bs[5];
        o.z = u[6].y + bs[6]; o.w = u[7].y + bs[7];
        *(float4*)(cp1 + 4) = o;
    }
}

// ---------------- fused 2-layer pipelined recurrence ----------------
#define FU_SMEM_BYTES (3 * 8 * HDIM * 4)   // 96KB: Wh0, Wi1, Wh1 slices [k][8c]

// butterfly reduction of 16 acc-pairs across 32 lanes -> 1 pair per lane
__device__ __forceinline__ ull reduce16(ull* a, int lane) {
    #pragma unroll
    for (int i = 0; i < 16; i++) {
        ull r = __shfl_xor_sync(0xffffffffu, a[i], 16);
        add2(a[i], r);
    }
    {
        int bit = lane & 1;
        #pragma unroll
        for (int i = 0; i < 8; i++) {
            ull snd = bit ? a[i] : a[i + 8];
            ull rcv = __shfl_xor_sync(0xffffffffu, snd, 1);
            a[i] = bit ? a[i + 8] : a[i];
            add2(a[i], rcv);
        }
    }
    {
        int bit = (lane >> 1) & 1;
        #pragma unroll
        for (int i = 0; i < 4; i++) {
            ull snd = bit ? a[i] : a[i + 4];
            ull rcv = __shfl_xor_sync(0xffffffffu, snd, 2);
            a[i] = bit ? a[i + 4] : a[i];
            add2(a[i], rcv);
        }
    }
    {
        int bit = (lane >> 2) & 1;
        #pragma unroll
        for (int i = 0; i < 2; i++) {
            ull snd = bit ? a[i] : a[i + 2];
            ull rcv = __shfl_xor_sync(0xffffffffu, snd, 4);
            a[i] = bit ? a[i + 2] : a[i];
            add2(a[i], rcv);
        }
    }
    {
        int bit = (lane >> 3) & 1;
        ull snd = bit ? a[0] : a[1];
        ull rcv = __shfl_xor_sync(0xffffffffu, snd, 8);
        a[0] = bit ? a[1] : a[0];
        add2(a[0], rcv);
    }
    return a[0];
}

__device__ __forceinline__ void norm_half(ull* dst, const ull* A0, const ull* A1,
                                          const ull* B0, const ull* B1, int half) {
    if (half == 0) {
        #pragma unroll
        for (int b = 0; b < 4; b++) {
            dst[0 + b] = A0[b]; dst[4 + b]  = A1[b];
            dst[8 + b] = B0[b]; dst[12 + b] = B1[b];
        }
    } else {
        #pragma unroll
        for (int b = 0; b < 4; b++) {
            dst[0 + b] = B0[b]; dst[4 + b]  = B1[b];
            dst[8 + b] = A0[b]; dst[12 + b] = A1[b];
        }
    }
}

// single-matrix 1024-dot (for the h2 recurrent term)
__device__ __forceinline__ ull dot_block(const float* __restrict__ Wsm,
                                         const char* __restrict__ hbase,
                                         int lane, int half) {
    const char* wbaseA = (const char*)Wsm + lane * 32 + half * 16;
    const char* wbaseB = (const char*)Wsm + lane * 32 + (1 - half) * 16;

    ull A0[4], A1[4], B0[4], B1[4];
    #pragma unroll
    for (int b = 0; b < 4; b++) { A0[b] = A1[b] = B0[b] = B1[b] = 0ull; }

    float4 hbuf[2][8];
    #pragma unroll
    for (int i = 0; i < 8; i++)
        hbuf[0][i] = ldcg_f4(hbase + i * 512);

    #pragma unroll
    for (int m = 0; m < 4; m++) {
        if (m < 3) {
            #pragma unroll
            for (int i = 0; i < 8; i++)
                hbuf[(m + 1) & 1][i] = ldcg_f4(hbase + ((m + 1) * 8 + i) * 512);
        }
        #pragma unroll
        for (int i = 0; i < 8; i++) {
            int koff = (m * 8 + i) * 1024;
            ulonglong2 wA = *(const ulonglong2*)(wbaseA + koff);
            ulonglong2 wB = *(const ulonglong2*)(wbaseB + koff);
            float4 h = hbuf[m & 1][i];
            ull s0 = splat2(h.x), s1 = splat2(h.y);
            ull s2 = splat2(h.z), s3 = splat2(h.w);
            ffma2(A0[0], s0, wA.x); ffma2(A1[0], s0, wA.y);
            ffma2(B0[0], s0, wB.x); ffma2(B1[0], s0, wB.y);
            ffma2(A0[1], s1, wA.x); ffma2(A1[1], s1, wA.y);
            ffma2(B0[1], s1, wB.x); ffma2(B1[1], s1, wB.y);
            ffma2(A0[2], s2, wA.x); ffma2(A1[2], s2, wA.y);
            ffma2(B0[2], s2, wB.x); ffma2(B1[2], s2, wB.y);
            ffma2(A0[3], s3, wA.x); ffma2(A1[3], s3, wA.y);
            ffma2(B0[3], s3, wB.x); ffma2(B1[3], s3, wB.y);
        }
    }

    ull a[16];
    norm_half(a, A0, A1, B0, B1, half);
    return reduce16(a, lane);
}

// dual-matrix 1024-dot: read h ONCE, accumulate for Wa (Whh0) and Wz (Wih1)
struct DPair { ull a; ull z; };

__device__ __forceinline__ DPair dot_block_dual(
    const float* __restrict__ Wa, const float* __restrict__ Wz,
    const char* __restrict__ hbase, int lane, int half)
{
    const char* waA = (const char*)Wa + lane * 32 + half * 16;
    const char* waB = (const char*)Wa + lane * 32 + (1 - half) * 16;
    const char* wzA = (const char*)Wz + lane * 32 + half * 16;
    const char* wzB = (const char*)Wz + lane * 32 + (1 - half) * 16;

    ull aA0[4], aA1[4], aB0[4], aB1[4];
    ull zA0[4], zA1[4], zB0[4], zB1[4];
    #pragma unroll
    for (int b = 0; b < 4; b++) {
        aA0[b] = aA1[b] = aB0[b] = aB1[b] = 0ull;
        zA0[b] = zA1[b] = zB0[b] = zB1[b] = 0ull;
    }

    // 8 chunks of 4 k-indices; single-chunk-ahead prefetch (reg pressure)
    float4 hbuf[2][4];
    #pragma unroll
    for (int i = 0; i < 4; i++)
        hbuf[0][i] = ldcg_f4(hbase + i * 512);

    #pragma unroll
    for (int c = 0; c < 8; c++) {
        if (c < 7) {
            #pragma unroll
            for (int i = 0; i < 4; i++)
                hbuf[(c + 1) & 1][i] = ldcg_f4(hbase + ((c + 1) * 4 + i) * 512);
        }
        #pragma unroll
        for (int i = 0; i < 4; i++) {
            int koff = (c * 4 + i) * 1024;
            ulonglong2 wa1 = *(const ulonglong2*)(waA + koff);
            ulonglong2 wa2 = *(const ulonglong2*)(waB + koff);
            ulonglong2 wz1 = *(const ulonglong2*)(wzA + koff);
            ulonglong2 wz2 = *(const ulonglong2*)(wzB + koff);
            float4 h = hbuf[c & 1][i];
            ull s0 = splat2(h.x), s1 = splat2(h.y);
            ull s2 = splat2(h.z), s3 = splat2(h.w);

            ffma2(aA0[0], s0, wa1.x); ffma2(aA1[0], s0, wa1.y);
            ffma2(aB0[0], s0, wa2.x); ffma2(aB1[0], s0, wa2.y);
            ffma2(zA0[0], s0, wz1.x); ffma2(zA1[0], s0, wz1.y);
            ffma2(zB0[0], s0, wz2.x); ffma2(zB1[0], s0, wz2.y);

            ffma2(aA0[1], s1, wa1.x); ffma2(aA1[1], s1, wa1.y);
            ffma2(aB0[1], s1, wa2.x); ffma2(aB1[1], s1, wa2.y);
            ffma2(zA0[1], s1, wz1.x); ffma2(zA1[1], s1, wz1.y);
            ffma2(zB0[1], s1, wz2.x); ffma2(zB1[1], s1, wz2.y);

            ffma2(aA0[2], s2, wa1.x); ffma2(aA1[2], s2, wa1.y);
            ffma2(aB0[2], s2, wa2.x); ffma2(aB1[2], s2, wa2.y);
            ffma2(zA0[2], s2, wz1.x); ffma2(zA1[2], s2, wz1.y);
            ffma2(zB0[2], s2, wz2.x); ffma2(zB1[2], s2, wz2.y);

            ffma2(aA0[3], s3, wa1.x); ffma2(aA1[3], s3, wa1.y);
            ffma2(aB0[3], s3, wa2.x); ffma2(aB1[3], s3, wa2.y);
            ffma2(zA0[3], s3, wz1.x); ffma2(zA1[3], s3, wz1.y);
            ffma2(zB0[3], s3, wz2.x); ffma2(zB1[3], s3, wz2.y);
        }
    }

    DPair r;
    {
        ull a[16];
        norm_half(a, aA0, aA1, aB0, aB1, half);
        r.a = reduce16(a, lane);
    }
    {
        ull a[16];
        norm_half(a, zA0, zA1, zB0, zB1, half);
        r.z = reduce16(a, lane);
    }
    return r;
}

__device__ __forceinline__ void poll_all(const unsigned* __restrict__ fpp,
                                         unsigned tt, int lane) {
    for (;;) {
        unsigned f0, f1, f2, f3;
        asm volatile("ld.acquire.gpu.u32 %0, [%1];" : "=r"(f0) : "l"(fpp + lane));
        asm volatile("ld.acquire.gpu.u32 %0, [%1];" : "=r"(f1) : "l"(fpp + lane + 32));
        asm volatile("ld.acquire.gpu.u32 %0, [%1];" : "=r"(f2) : "l"(fpp + lane + 64));
        asm volatile("ld.acquire.gpu.u32 %0, [%1];" : "=r"(f3) : "l"(fpp + lane + 96));
        bool ok = (f0 >= tt) & (f1 >= tt) & (f2 >= tt) & (f3 >= tt);
        if (__all_sync(0xffffffffu, ok)) break;
    }
}

__global__ __launch_bounds__(256, 1) void recur_fused(
    const float* __restrict__ xw0,   // [i*B+b, H] layer-0 input projection
    const float* __restrict__ Whh0,
    const float* __restrict__ Wih1,
    const float* __restrict__ Whh1,
    const float* __restrict__ bih1,
    const float* __restrict__ bhh1,
    float* __restrict__ out)         // [B, T, H]
{
    extern __shared__ __align__(16) float sm[];
    float* Wh0 = sm;                 // [k][8c]
    float* Wi1 = sm + 8 * HDIM;
    float* Wh1 = sm + 16 * HDIM;

    int tid  = threadIdx.x;
    int cb   = blockIdx.x;
    int lane = tid & 31;
    int sg   = tid >> 5;

    // load the three 8-col weight slices, [k][c] layout
    for (int idx = tid; idx < 8 * HDIM; idx += 256) {
        int c = idx >> 10;
        int k = idx & 1023;
        Wh0[k * 8 + c] = __ldg(Whh0 + (size_t)(cb * 8 + c) * HDIM + k);
        Wi1[k * 8 + c] = __ldg(Wih1 + (size_t)(cb * 8 + c) * HDIM + k);
        Wh1[k * 8 + c] = __ldg(Whh1 + (size_t)(cb * 8 + c) * HDIM + k);
    }
    __syncthreads();

    int half = (lane >> 2) & 1;
    int cp_r = 2 * (lane & 1) + ((lane >> 1) & 1);
    int b_r  = 2 * ((lane >> 2) & 1) + ((lane >> 3) & 1);
    int col0 = cb * 8 + 2 * cp_r;
    int gb   = sg * 4 + b_r;

    const unsigned* fpp1 = g_fh1 + sg * 128;
    const unsigned* fpp2 = g_fh2 + sg * 128;
    unsigned* myf1 = g_fh1 + sg * 128 + cb;
    unsigned* myf2 = g_fh2 + sg * 128 + cb;

    float2 bsum;
    bsum.x = __ldg(bih1 + col0) + __ldg(bhh1 + col0);
    bsum.y = __ldg(bih1 + col0 + 1) + __ldg(bhh1 + col0 + 1);

    for (int i = 0; i <= TDIM; i++) {
        float2 xv = make_float2(0.f, 0.f);
        if (i < TDIM)
            xv = *(const float2*)(xw0 + ((size_t)i * BDIM + gb) * HDIM + col0);

        // ---- shared read of h1(i-1): dual dot (Whh0 + Wih1) ----
        DPair dp;
        dp.a = 0ull; dp.z = 0ull;
        if (i > 0) {
            poll_all(fpp1, (unsigned)i, lane);
            const char* hb = (const char*)&g_hp1[sg][(i - 1) & 3][0] + lane * 16;
            dp = dot_block_dual(Wh0, Wi1, hb, lane, half);
        }

        // ---- part A: h1(i) ----
        if (i < TDIM) {
            float v0, v1;
            if (i == 0) {
                v0 = tanhf(xv.x);
                v1 = tanhf(xv.y);
            } else {
                float2 u = unpack2(dp.a);
                v0 = tanhf(xv.x + u.x);
                v1 = tanhf(xv.y + u.y);
            }
            if (lane < 16) {
                float* pb = &g_hp1[sg][i & 3][0];
                pb[(col0 + 0) * 4 + b_r] = v0;
                pb[(col0 + 1) * 4 + b_r] = v1;
            }
            __syncwarp();
            if (lane == 0) {
                asm volatile("st.release.gpu.u32 [%0], %1;"
                             :: "l"(myf1), "r"((unsigned)(i + 1)));
            }
        }

        // ---- part B: h2(s) for s = i-1 ----
        if (i > 0) {
            int s = i - 1;
            float2 uz = unpack2(dp.z);
            float o0 = bsum.x + uz.x;
            float o1 = bsum.y + uz.y;

            if (s > 0) {
                poll_all(fpp2, (unsigned)s, lane);
                const char* hb2 = (const char*)&g_hp2[sg][(s - 1) & 3][0] + lane * 16;
                float2 ur = unpack2(dot_block(Wh1, hb2, lane, half));
                o0 += ur.x;
                o1 += ur.y;
            }
            float v0 = tanhf(o0);
            float v1 = tanhf(o1);

            if (lane < 16) {
                *(float2*)(out + ((size_t)gb * TDIM + s) * HDIM + col0)
                    = make_float2(v0, v1);
                float* pb = &g_hp2[sg][s & 3][0];
                pb[(col0 + 0) * 4 + b_r] = v0;
                pb[(col0 + 1) * 4 + b_r] = v1;
            }
            __syncwarp();
            if (lane == 0) {
                asm volatile("st.release.gpu.u32 [%0], %1;"
                             :: "l"(myf2), "r"((unsigned)(s + 1)));
            }
        }
    }
}

// ---------------- launch ----------------
extern "C" void kernel_launch(void* const* d_in, const int* in_sizes, int n_in,
                              void* d_out, int out_size)
{
    const float* x    = (const float*)d_in[0];
    const float* Wih0 = (const float*)d_in[1];
    const float* Whh0 = (const float*)d_in[2];
    const float* bih0 = (const float*)d_in[3];
    const float* bhh0 = (const float*)d_in[4];
    const float* Wih1 = (const float*)d_in[5];
    const float* Whh1 = (const float*)d_in[6];
    const float* bih1 = (const float*)d_in[7];
    const float* bhh1 = (const float*)d_in[8];
    float* out = (float*)d_out;

    float *xT, *xw;
    cudaGetSymbolAddress((void**)&xT, g_xT);
    cudaGetSymbolAddress((void**)&xw, g_xw);

    cudaFuncSetAttribute(recur_fused, cudaFuncAttributeMaxDynamicSharedMemorySize,
                         FU_SMEM_BYTES);

    init_flags<<<4, 256>>>();
    transpose_x<<<MDIM, 128>>>(x);
    gemm_bias<<<dim3(HDIM / 128, MDIM / 128), 256>>>(xT, Wih0, bih0, bhh0, xw, IDIM);
    recur_fused<<<128, 256, FU_SMEM_BYTES>>>(xw, Whh0, Wih1, Whh1, bih1, bhh1, out);
}

// round 11
// speedup vs baseline: 2.7771x; 1.0495x over previous
#include <cuda_runtime.h>
#include <cuda_bf16.h>
#include <stdint.h>

typedef unsigned long long ull;

// Problem dims
#define BDIM 32
#define TDIM 512
#define IDIM 512
#define HDIM 1024

// ---------------- scratch (static device globals; no allocation) ----------------
// x staged as [t][grp][k][4 local b]  (512*8*512*4 floats = 32MB)
__device__ float g_xs[(size_t)TDIM * 8 * IDIM * 4];
__device__ float g_hp1[8][4][HDIM * 4];       // h1 ring: [grp][slot][k][4 local b]
__device__ float g_hp2[8][4][HDIM * 4];       // h2 ring

__device__ unsigned g_fh1[1024];              // [grp][cb] layer-0 progress
__device__ unsigned g_fh2[1024];              // layer-1 progress

// ---------------- f32x2 helpers ----------------
__device__ __forceinline__ void ffma2(ull& d, ull a, ull b) {
    asm("fma.rn.f32x2 %0, %1, %2, %0;" : "+l"(d) : "l"(a), "l"(b));
}
__device__ __forceinline__ void add2(ull& d, ull a) {
    asm("add.rn.f32x2 %0, %0, %1;" : "+l"(d) : "l"(a));
}
__device__ __forceinline__ ull splat2(float x) {
    ull r;
    asm("mov.b64 %0, {%1, %1};" : "=l"(r) : "f"(x));
    return r;
}
__device__ __forceinline__ float2 unpack2(ull v) {
    float lo, hi;
    asm("mov.b64 {%0, %1}, %2;" : "=f"(lo), "=f"(hi) : "l"(v));
    return make_float2(lo, hi);
}
__device__ __forceinline__ float4 ldcg_f4(const void* p) {
    float4 v;
    asm volatile("ld.global.cg.v4.f32 {%0,%1,%2,%3}, [%4];"
                 : "=f"(v.x), "=f"(v.y), "=f"(v.z), "=f"(v.w) : "l"(p));
    return v;
}

// ---------------- init flags (inside graph; replayed every run) ----------------
__global__ void init_flags() {
    int i = blockIdx.x * blockDim.x + threadIdx.x;
    if (i < 1024) {
        g_fh1[i] = 0;
        g_fh2[i] = 0;
    }
}

// ---------------- stage x[B,T,I] -> g_xs[t][grp][k][4b] ----------------
__global__ __launch_bounds__(256) void stage_x(const float* __restrict__ x) {
    int t = blockIdx.x;
    int tid = threadIdx.x;
    for (int idx = tid; idx < 8 * IDIM; idx += 256) {
        int sg = idx >> 9;          // group
        int k  = idx & 511;
        const float* xb = x + (size_t)t * IDIM + k;
        float4 v;
        v.x = xb[(size_t)(sg * 4 + 0) * TDIM * IDIM];
        v.y = xb[(size_t)(sg * 4 + 1) * TDIM * IDIM];
        v.z = xb[(size_t)(sg * 4 + 2) * TDIM * IDIM];
        v.w = xb[(size_t)(sg * 4 + 3) * TDIM * IDIM];
        *(float4*)(g_xs + (((size_t)t * 8 + sg) << 11) + k * 4) = v;
    }
}

// ---------------- acc structure and helpers ----------------
struct Accs { ull v[16]; };   // [A0 b0..3 | A1 b0..3 | B0 b0..3 | B1 b0..3]

__device__ __forceinline__ void zero_accs(Accs& a) {
    #pragma unroll
    for (int i = 0; i < 16; i++) a.v[i] = 0ull;
}

__device__ __forceinline__ void acc_step(Accs& a, ulonglong2 w1, ulonglong2 w2,
                                         float4 h) {
    ull s0 = splat2(h.x), s1 = splat2(h.y);
    ull s2 = splat2(h.z), s3 = splat2(h.w);
    ffma2(a.v[0],  s0, w1.x); ffma2(a.v[4],  s0, w1.y);
    ffma2(a.v[8],  s0, w2.x); ffma2(a.v[12], s0, w2.y);
    ffma2(a.v[1],  s1, w1.x); ffma2(a.v[5],  s1, w1.y);
    ffma2(a.v[9],  s1, w2.x); ffma2(a.v[13], s1, w2.y);
    ffma2(a.v[2],  s2, w1.x); ffma2(a.v[6],  s2, w1.y);
    ffma2(a.v[10], s2, w2.x); ffma2(a.v[14], s2, w2.y);
    ffma2(a.v[3],  s3, w1.x); ffma2(a.v[7],  s3, w1.y);
    ffma2(a.v[11], s3, w2.x); ffma2(a.v[15], s3, w2.y);
}

// butterfly reduction of 16 acc-pairs across 32 lanes -> 1 pair per lane
__device__ __forceinline__ ull reduce16(ull* a, int lane) {
    #pragma unroll
    for (int i = 0; i < 16; i++) {
        ull r = __shfl_xor_sync(0xffffffffu, a[i], 16);
        add2(a[i], r);
    }
    {
        int bit = lane & 1;
        #pragma unroll
        for (int i = 0; i < 8; i++) {
            ull snd = bit ? a[i] : a[i + 8];
            ull rcv = __shfl_xor_sync(0xffffffffu, snd, 1);
            a[i] = bit ? a[i + 8] : a[i];
            add2(a[i], rcv);
        }
    }
    {
        int bit = (lane >> 1) & 1;
        #pragma unroll
        for (int i = 0; i < 4; i++) {
            ull snd = bit ? a[i] : a[i + 4];
            ull rcv = __shfl_xor_sync(0xffffffffu, snd, 2);
            a[i] = bit ? a[i + 4] : a[i];
            add2(a[i], rcv);
        }
    }
    {
        int bit = (lane >> 2) & 1;
        #pragma unroll
        for (int i = 0; i < 2; i++) {
            ull snd = bit ? a[i] : a[i + 2];
            ull rcv = __shfl_xor_sync(0xffffffffu, snd, 4);
            a[i] = bit ? a[i + 2] : a[i];
            add2(a[i], rcv);
        }
    }
    {
        int bit = (lane >> 3) & 1;
        ull snd = bit ? a[0] : a[1];
        ull rcv = __shfl_xor_sync(0xffffffffu, snd, 8);
        a[0] = bit ? a[1] : a[0];
        add2(a[0], rcv);
    }
    return a[0];
}

// map Accs (lane-local A/B halves) to physical col-pair order, then reduce
__device__ __forceinline__ ull norm_reduce(const Accs& ac, int lane, int half) {
    ull a[16];
    if (half == 0) {
        #pragma unroll
        for (int i = 0; i < 16; i++) a[i] = ac.v[i];
    } else {
        #pragma unroll
        for (int i = 0; i < 8; i++) {
            a[i]     = ac.v[i + 8];
            a[i + 8] = ac.v[i];
        }
    }
    return reduce16(a, lane);
}

// single-matrix 1024-dot (for the h2 recurrent term)
__device__ __forceinline__ ull dot_block(const float* __restrict__ Wsm,
                                         const char* __restrict__ hbase,
                                         int lane, int half) {
    const char* wA = (const char*)Wsm + lane * 32 + half * 16;
    const char* wB = (const char*)Wsm + lane * 32 + (1 - half) * 16;

    Accs ac;
    zero_accs(ac);

    float4 hbuf[2][4];
    #pragma unroll
    for (int j = 0; j < 4; j++)
        hbuf[0][j] = ldcg_f4(hbase + j * 512);

    #pragma unroll
    for (int c = 0; c < 8; c++) {
        if (c < 7) {
            #pragma unroll
            for (int j = 0; j < 4; j++)
                hbuf[(c + 1) & 1][j] = ldcg_f4(hbase + ((c + 1) * 4 + j) * 512);
        }
        #pragma unroll
        for (int j = 0; j < 4; j++) {
            int koff = (c * 4 + j) * 1024;
            ulonglong2 w1 = *(const ulonglong2*)(wA + koff);
            ulonglong2 w2 = *(const ulonglong2*)(wB + koff);
            acc_step(ac, w1, w2, hbuf[c & 1][j]);
        }
    }
    return norm_reduce(ac, lane, half);
}

__device__ __forceinline__ void poll_all(const unsigned* __restrict__ fpp,
                                         unsigned tt, int lane) {
    for (;;) {
        unsigned f0, f1, f2, f3;
        asm volatile("ld.acquire.gpu.u32 %0, [%1];" : "=r"(f0) : "l"(fpp + lane));
        asm volatile("ld.acquire.gpu.u32 %0, [%1];" : "=r"(f1) : "l"(fpp + lane + 32));
        asm volatile("ld.acquire.gpu.u32 %0, [%1];" : "=r"(f2) : "l"(fpp + lane + 64));
        asm volatile("ld.acquire.gpu.u32 %0, [%1];" : "=r"(f3) : "l"(fpp + lane + 96));
        bool ok = (f0 >= tt) & (f1 >= tt) & (f2 >= tt) & (f3 >= tt);
        if (__all_sync(0xffffffffu, ok)) break;
    }
}

// ---------------- fully fused: xw0 GEMM + 2-layer pipelined recurrence ----------------
// smem: Wh0 (32KB) + Wi1 (32KB) + Wh1 (32KB) + Wi0 (16KB) = 112KB
#define FU_SMEM_BYTES ((3 * 8 * HDIM + 8 * IDIM) * 4)

__global__ __launch_bounds__(256, 1) void recur_fused(
    const float* __restrict__ xs,    // staged x: [t][grp][k][4b]
    const float* __restrict__ Whh0,
    const float* __restrict__ Wih0,  // [H, I]
    const float* __restrict__ Wih1,
    const float* __restrict__ Whh1,
    const float* __restrict__ bih0,
    const float* __restrict__ bhh0,
    const float* __restrict__ bih1,
    const float* __restrict__ bhh1,
    float* __restrict__ out)         // [B, T, H]
{
    extern __shared__ __align__(16) float sm[];
    float* Wh0 = sm;                       // [k][8c], k<1024
    float* Wi1 = sm + 8 * HDIM;
    float* Wh1 = sm + 16 * HDIM;
    float* Wi0 = sm + 24 * HDIM;           // [k][8c], k<512

    int tid  = threadIdx.x;
    int cb   = blockIdx.x;
    int lane = tid & 31;
    int sg   = tid >> 5;

    // load the weight slices, [k][c] layout
    for (int idx = tid; idx < 8 * HDIM; idx += 256) {
        int c = idx >> 10;
        int k = idx & 1023;
        Wh0[k * 8 + c] = __ldg(Whh0 + (size_t)(cb * 8 + c) * HDIM + k);
        Wi1[k * 8 + c] = __ldg(Wih1 + (size_t)(cb * 8 + c) * HDIM + k);
        Wh1[k * 8 + c] = __ldg(Whh1 + (size_t)(cb * 8 + c) * HDIM + k);
    }
    for (int idx = tid; idx < 8 * IDIM; idx += 256) {
        int c = idx >> 9;
        int k = idx & 511;
        Wi0[k * 8 + c] = __ldg(Wih0 + (size_t)(cb * 8 + c) * IDIM + k);
    }
    __syncthreads();

    int half = (lane >> 2) & 1;
    int cp_r = 2 * (lane & 1) + ((lane >> 1) & 1);
    int b_r  = 2 * ((lane >> 2) & 1) + ((lane >> 3) & 1);
    int col0 = cb * 8 + 2 * cp_r;
    int gb   = sg * 4 + b_r;

    const unsigned* fpp1 = g_fh1 + sg * 128;
    const unsigned* fpp2 = g_fh2 + sg * 128;
    unsigned* myf1 = g_fh1 + sg * 128 + cb;
    unsigned* myf2 = g_fh2 + sg * 128 + cb;

    float2 b0sum, b1sum;
    b0sum.x = __ldg(bih0 + col0) + __ldg(bhh0 + col0);
    b0sum.y = __ldg(bih0 + col0 + 1) + __ldg(bhh0 + col0 + 1);
    b1sum.x = __ldg(bih1 + col0) + __ldg(bhh1 + col0);
    b1sum.y = __ldg(bih1 + col0 + 1) + __ldg(bhh1 + col0 + 1);

    const char* wi0A = (const char*)Wi0 + lane * 32 + half * 16;
    const char* wi0B = (const char*)Wi0 + lane * 32 + (1 - half) * 16;
    const char* wh0A = (const char*)Wh0 + lane * 32 + half * 16;
    const char* wh0B = (const char*)Wh0 + lane * 32 + (1 - half) * 16;
    const char* wi1A = (const char*)Wi1 + lane * 32 + half * 16;
    const char* wi1B = (const char*)Wi1 + lane * 32 + (1 - half) * 16;

    for (int i = 0; i <= TDIM; i++) {
        int s = i - 1;

        // ---- x-dot: seed a-accs with Wih0 . x(i)  (no dependencies) ----
        Accs xa;
        zero_accs(xa);
        if (i < TDIM) {
            const char* xb = (const char*)(xs + (((size_t)i * 8 + sg) << 11))
                             + lane * 16;
            float4 xbuf[2][4];
            #pragma unroll
            for (int j = 0; j < 4; j++)
                xbuf[0][j] = ldcg_f4(xb + j * 512);
            #pragma unroll
            for (int c = 0; c < 4; c++) {
                if (c < 3) {
                    #pragma unroll
                    for (int j = 0; j < 4; j++)
                        xbuf[(c + 1) & 1][j] = ldcg_f4(xb + ((c + 1) * 4 + j) * 512);
                }
                #pragma unroll
                for (int j = 0; j < 4; j++) {
                    int koff = (c * 4 + j) * 1024;
                    ulonglong2 w1 = *(const ulonglong2*)(wi0A + koff);
                    ulonglong2 w2 = *(const ulonglong2*)(wi0B + koff);
                    acc_step(xa, w1, w2, xbuf[c & 1][j]);
                }
            }
        }

        // ---- combined polls: both chains' waits overlap ----
        if (i > 0) {
            poll_all(fpp1, (unsigned)i, lane);
            if (s > 0) poll_all(fpp2, (unsigned)s, lane);
        }

        // ---- dual dot over h1(i-1): xa += Wh0.h1 ; za = Wi1.h1 ----
        Accs za;
        zero_accs(za);
        if (i > 0) {
            const char* hb = (const char*)&g_hp1[sg][(i - 1) & 3][0] + lane * 16;
            float4 hbuf[2][4];
            #pragma unroll
            for (int j = 0; j < 4; j++)
                hbuf[0][j] = ldcg_f4(hb + j * 512);
            #pragma unroll
            for (int c = 0; c < 8; c++) {
                if (c < 7) {
                    #pragma unroll
                    for (int j = 0; j < 4; j++)
                        hbuf[(c + 1) & 1][j] = ldcg_f4(hb + ((c + 1) * 4 + j) * 512);
                }
                #pragma unroll
                for (int j = 0; j < 4; j++) {
                    int koff = (c * 4 + j) * 1024;
                    float4 h = hbuf[c & 1][j];
                    ulonglong2 wa1 = *(const ulonglong2*)(wh0A + koff);
                    ulonglong2 wa2 = *(const ulonglong2*)(wh0B + koff);
                    acc_step(xa, wa1, wa2, h);
                    ulonglong2 wz1 = *(const ulonglong2*)(wi1A + koff);
                    ulonglong2 wz2 = *(const ulonglong2*)(wi1B + koff);
                    acc_step(za, wz1, wz2, h);
                }
            }
        }

        // ---- part A: h1(i) = tanh(bias0 + Wih0.x(i) + Whh0.h1(i-1)) ----
        if (i < TDIM) {
            float2 u = unpack2(norm_reduce(xa, lane, half));
            float v0 = tanhf(b0sum.x + u.x);
            float v1 = tanhf(b0sum.y + u.y);
            if (lane < 16) {
                float* pb = &g_hp1[sg][i & 3][0];
                pb[(col0 + 0) * 4 + b_r] = v0;
                pb[(col0 + 1) * 4 + b_r] = v1;
            }
            __syncwarp();
            if (lane == 0) {
                asm volatile("st.release.gpu.u32 [%0], %1;"
                             :: "l"(myf1), "r"((unsigned)(i + 1)));
            }
        }

        // ---- part B: h2(s) = tanh(bias1 + Wih1.h1(s) + Whh1.h2(s-1)) ----
        if (i > 0) {
            float2 uz = unpack2(norm_reduce(za, lane, half));
            float o0 = b1sum.x + uz.x;
            float o1 = b1sum.y + uz.y;

            if (s > 0) {
                const char* hb2 = (const char*)&g_hp2[sg][(s - 1) & 3][0] + lane * 16;
                float2 ur = unpack2(dot_block(Wh1, hb2, lane, half));
                o0 += ur.x;
                o1 += ur.y;
            }
            float v0 = tanhf(o0);
            float v1 = tanhf(o1);

            if (lane < 16) {
                *(float2*)(out + ((size_t)gb * TDIM + s) * HDIM + col0)
                    = make_float2(v0, v1);
                float* pb = &g_hp2[sg][s & 3][0];
                pb[(col0 + 0) * 4 + b_r] = v0;
                pb[(col0 + 1) * 4 + b_r] = v1;
            }
            __syncwarp();
            if (lane == 0) {
                asm volatile("st.release.gpu.u32 [%0], %1;"
                             :: "l"(myf2), "r"((unsigned)(s + 1)));
            }
        }
    }
}

// ---------------- launch ----------------
extern "C" void kernel_launch(void* const* d_in, const int* in_sizes, int n_in,
                              void* d_out, int out_size)
{
    const float* x    = (const float*)d_in[0];
    const float* Wih0 = (const float*)d_in[1];
    const float* Whh0 = (const float*)d_in[2];
    const float* bih0 = (const float*)d_in[3];
    const float* bhh0 = (const float*)d_in[4];
    const float* Wih1 = (const float*)d_in[5];
    const float* Whh1 = (const float*)d_in[6];
    const float* bih1 = (const float*)d_in[7];
    const float* bhh1 = (const float*)d_in[8];
    float* out = (float*)d_out;

    float* xs;
    cudaGetSymbolAddress((void**)&xs, g_xs);

    cudaFuncSetAttribute(recur_fused, cudaFuncAttributeMaxDynamicSharedMemorySize,
                         FU_SMEM_BYTES);

    init_flags<<<4, 256>>>();
    stage_x<<<TDIM, 256>>>(x);
    recur_fused<<<128, 256, FU_SMEM_BYTES>>>(xs, Whh0, Wih0, Wih1, Whh1,
                                             bih0, bhh0, bih1, bhh1, out);
}